// round 9
// baseline (speedup 1.0000x reference)
#include <cuda_runtime.h>
#include <cuda_bf16.h>
#include <stdint.h>

#define BATCH 32768
#define NIN   1024
#define NHID  2048

// ---- scratch (static __device__, no allocation) ----
__device__ __align__(256) __nv_bfloat16 g_xh [(size_t)BATCH*NIN];
__device__ __align__(256) __nv_bfloat16 g_xl [(size_t)BATCH*NIN];
__device__ __align__(256) __nv_bfloat16 g_w0h[(size_t)NHID*NIN];    // [n][k]
__device__ __align__(256) __nv_bfloat16 g_w0l[(size_t)NHID*NIN];
__device__ __align__(256) __nv_bfloat16 g_w1h[(size_t)NHID*NHID];
__device__ __align__(256) __nv_bfloat16 g_w1l[(size_t)NHID*NHID];
__device__ __align__(256) __nv_bfloat16 g_h0h[(size_t)BATCH*NHID];
__device__ __align__(256) __nv_bfloat16 g_h0l[(size_t)BATCH*NHID];
__device__ __align__(256) __nv_bfloat16 g_h1h[(size_t)BATCH*NHID];
__device__ __align__(256) __nv_bfloat16 g_h1l[(size_t)BATCH*NHID];

// ---- helpers ----
__device__ __forceinline__ uint32_t s2u(const void* p){
    return (uint32_t)__cvta_generic_to_shared(p);
}
__device__ __forceinline__ void cp16(uint32_t d, const void* s){
    asm volatile("cp.async.cg.shared.global [%0], [%1], 16;\n" :: "r"(d), "l"(s));
}
__device__ __forceinline__ void ldm4(uint32_t&r0,uint32_t&r1,uint32_t&r2,uint32_t&r3,uint32_t a){
    asm volatile("ldmatrix.sync.aligned.m8n8.x4.shared.b16 {%0,%1,%2,%3},[%4];\n"
        : "=r"(r0),"=r"(r1),"=r"(r2),"=r"(r3) : "r"(a));
}
__device__ __forceinline__ void mma16816(float* c, const uint32_t* a, const uint32_t* b){
    asm volatile("mma.sync.aligned.m16n8k16.row.col.f32.bf16.bf16.f32 "
        "{%0,%1,%2,%3},{%4,%5,%6,%7},{%8,%9},{%0,%1,%2,%3};\n"
        : "+f"(c[0]),"+f"(c[1]),"+f"(c[2]),"+f"(c[3])
        : "r"(a[0]),"r"(a[1]),"r"(a[2]),"r"(a[3]),"r"(b[0]),"r"(b[1]));
}
__device__ __forceinline__ float eluf(float x){ return x > 0.f ? x : (__expf(x) - 1.f); }
__device__ __forceinline__ void split_bf16(float v, __nv_bfloat16& h, __nv_bfloat16& l){
    h = __float2bfloat16(v);
    l = __float2bfloat16(v - __bfloat162float(h));
}

// ---- tile geometry ----
#define BM 128
#define BN 128
#define BK 32
#define ROWB 80            // 64B data + 16B pad -> conflict-free ldmatrix
#define TILEB (128*ROWB)   // 10240 B per plane-stage
#define NSTAGE 4
#define SM_TILE(p, st) ((uint32_t)(((st)*4 + (p)) * TILEB))
#define SMEM_SZ (NSTAGE*4*TILEB)   // 163840

// fragment set for one ks half-chunk
struct Frag {
    uint32_t ah[2][4], al[2][4];
    uint32_t bh[4][2], bl[4][2];
};

// C = elu(A @ BT^T + bias); split-bf16 hi/lo planes; fp32 accum.
// 512 threads, 16 warps (4x4, 32x32 warp tiles), 4-stage cp.async pipeline,
// PAIR-WISE chunk processing: one wait+sync per 2 chunks, fully-covered loads,
// register double-buffered fragments, term-major mma (acc reuse dist = 8).
__global__ void __launch_bounds__(512,1)
gemm_split(const __nv_bfloat16* __restrict__ Ah, const __nv_bfloat16* __restrict__ Al,
           const __nv_bfloat16* __restrict__ Bh, const __nv_bfloat16* __restrict__ Bl,
           const float* __restrict__ bias,
           __nv_bfloat16* __restrict__ Ch, __nv_bfloat16* __restrict__ Cl,
           int M, int N, int K)
{
    extern __shared__ __align__(16) unsigned char sm[];
    const uint32_t sb = s2u(sm);
    const int tid = threadIdx.x;
    const int m0 = blockIdx.y * BM;
    const int n0 = blockIdx.x * BN;
    const int KT = K / BK;   // even for all our K

    const int lrow = tid >> 2;
    const int lc   = tid & 3;
    const uint32_t dso = (uint32_t)(lrow*ROWB + lc*16);
    const __nv_bfloat16* pAh = Ah + (size_t)(m0+lrow)*K + lc*8;
    const __nv_bfloat16* pAl = Al + (size_t)(m0+lrow)*K + lc*8;
    const __nv_bfloat16* pBh = Bh + (size_t)(n0+lrow)*K + lc*8;
    const __nv_bfloat16* pBl = Bl + (size_t)(n0+lrow)*K + lc*8;

    auto load = [&](int kt, int st){
        const int kk = kt * BK;
        cp16(sb + SM_TILE(0,st) + dso, pAh + kk);
        cp16(sb + SM_TILE(1,st) + dso, pAl + kk);
        cp16(sb + SM_TILE(2,st) + dso, pBh + kk);
        cp16(sb + SM_TILE(3,st) + dso, pBl + kk);
        asm volatile("cp.async.commit_group;\n" ::: "memory");
    };

    const int warp = tid >> 5, lane = tid & 31;
    const int wr = warp >> 2, wc = warp & 3;

    const int a_row  = wr*32 + (lane & 15);
    const int a_colb = (lane >> 4) * 16;
    const int b_row  = wc*32 + (lane >> 4)*8 + (lane & 7);
    const int b_colb = ((lane >> 3) & 1) * 16;

    auto ldfrags = [&](int st, int ks, Frag& f){
        const uint32_t abh = sb + SM_TILE(0, st);
        const uint32_t abl = sb + SM_TILE(1, st);
        const uint32_t bbh = sb + SM_TILE(2, st);
        const uint32_t bbl = sb + SM_TILE(3, st);
        #pragma unroll
        for (int i = 0; i < 2; i++){
            const uint32_t ro = (uint32_t)(a_row + i*16)*ROWB + a_colb + ks*32;
            ldm4(f.ah[i][0],f.ah[i][1],f.ah[i][2],f.ah[i][3], abh + ro);
            ldm4(f.al[i][0],f.al[i][1],f.al[i][2],f.al[i][3], abl + ro);
        }
        #pragma unroll
        for (int p = 0; p < 2; p++){
            const uint32_t ro = (uint32_t)(b_row + p*16)*ROWB + b_colb + ks*32;
            uint32_t r0,r1,r2,r3;
            ldm4(r0,r1,r2,r3, bbh + ro);
            f.bh[p*2][0]=r0; f.bh[p*2][1]=r1; f.bh[p*2+1][0]=r2; f.bh[p*2+1][1]=r3;
            ldm4(r0,r1,r2,r3, bbl + ro);
            f.bl[p*2][0]=r0; f.bl[p*2][1]=r1; f.bl[p*2+1][0]=r2; f.bl[p*2+1][1]=r3;
        }
    };

    float acc[2][4][4];
    #pragma unroll
    for (int i=0;i<2;i++)
        #pragma unroll
        for (int j=0;j<4;j++)
            #pragma unroll
            for (int k=0;k<4;k++) acc[i][j][k] = 0.f;

    // term-major: same-acc mmas are 8 apart -> HMMA RAW latency hidden
    auto mma3 = [&](const Frag& f){
        #pragma unroll
        for (int t = 0; t < 3; t++){
            const uint32_t (*fa)[4] = (t == 2) ? f.al : f.ah;
            const uint32_t (*fb)[2] = (t == 1) ? f.bl : f.bh;
            #pragma unroll
            for (int i = 0; i < 2; i++)
                #pragma unroll
                for (int j = 0; j < 4; j++)
                    mma16816(acc[i][j], fa[i], fb[j]);
        }
    };

    load(0, 0);
    load(1, 1);

    Frag F0, F1;
    for (int kt = 0; kt < KT; kt += 2){
        asm volatile("cp.async.wait_group 0;\n" ::: "memory");
        __syncthreads();
        if (kt + 2 < KT) load(kt + 2, (kt + 2) & 3);
        if (kt + 3 < KT) load(kt + 3, (kt + 3) & 3);
        const int st0 = kt & 3, st1 = (kt + 1) & 3;

        ldfrags(st0, 0, F0);
        ldfrags(st0, 1, F1);   // LDSM in flight during...
        mma3(F0);              // ...this mma burst
        ldfrags(st1, 0, F0);
        mma3(F1);
        ldfrags(st1, 1, F1);
        mma3(F0);
        mma3(F1);
    }

    // epilogue: bias + elu -> hi/lo bf16 planes
    const int gid = lane >> 2, tig = lane & 3;
    #pragma unroll
    for (int i = 0; i < 2; i++){
        const int mrow = m0 + wr*32 + i*16 + gid;
        #pragma unroll
        for (int j = 0; j < 4; j++){
            const int n = n0 + wc*32 + j*8 + tig*2;
            const float2 bv = *(const float2*)&bias[n];
            float v[4] = {acc[i][j][0] + bv.x, acc[i][j][1] + bv.y,
                          acc[i][j][2] + bv.x, acc[i][j][3] + bv.y};
            v[0]=eluf(v[0]); v[1]=eluf(v[1]); v[2]=eluf(v[2]); v[3]=eluf(v[3]);
            __nv_bfloat16 h[4], l[4];
            #pragma unroll
            for (int q = 0; q < 4; q++) split_bf16(v[q], h[q], l[q]);
            const size_t o0 = (size_t)mrow*N + n, o1 = (size_t)(mrow+8)*N + n;
            *(__nv_bfloat162*)&Ch[o0] = *(__nv_bfloat162*)&h[0];
            *(__nv_bfloat162*)&Cl[o0] = *(__nv_bfloat162*)&l[0];
            *(__nv_bfloat162*)&Ch[o1] = *(__nv_bfloat162*)&h[2];
            *(__nv_bfloat162*)&Cl[o1] = *(__nv_bfloat162*)&l[2];
        }
    }
}

// fp32 x -> hi/lo bf16 planes
__global__ void cvt_x_k(const float* __restrict__ x,
                        __nv_bfloat16* __restrict__ xh, __nv_bfloat16* __restrict__ xl){
    size_t i = (size_t)blockIdx.x * blockDim.x + threadIdx.x;
    float4 v = ((const float4*)x)[i];
    __nv_bfloat16 h[4], l[4];
    split_bf16(v.x, h[0], l[0]); split_bf16(v.y, h[1], l[1]);
    split_bf16(v.z, h[2], l[2]); split_bf16(v.w, h[3], l[3]);
    ((uint2*)xh)[i] = *(uint2*)h;
    ((uint2*)xl)[i] = *(uint2*)l;
}

// w[k][n] fp32 -> wt hi/lo [n][k] bf16
__global__ void tr_cvt_k(const float* __restrict__ w,
                         __nv_bfloat16* __restrict__ wth, __nv_bfloat16* __restrict__ wtl,
                         int K, int N){
    __shared__ float t[32][33];
    const int n0 = blockIdx.x*32, k0 = blockIdx.y*32;
    #pragma unroll
    for (int r = threadIdx.y; r < 32; r += 8)
        t[r][threadIdx.x] = w[(size_t)(k0+r)*N + n0 + threadIdx.x];
    __syncthreads();
    #pragma unroll
    for (int r = threadIdx.y; r < 32; r += 8){
        float v = t[threadIdx.x][r];
        __nv_bfloat16 h, l; split_bf16(v, h, l);
        const size_t o = (size_t)(n0+r)*K + k0 + threadIdx.x;
        wth[o] = h; wtl[o] = l;
    }
}

// layer 3: warp-per-row matvec (hi+lo reconstruct) + sigmoid + alpha
__global__ void final_k(const __nv_bfloat16* __restrict__ hh, const __nv_bfloat16* __restrict__ hl,
                        const float* __restrict__ w2, const float* __restrict__ b2,
                        float* __restrict__ out){
    const int gw   = (blockIdx.x*blockDim.x + threadIdx.x) >> 5;
    const int lane = threadIdx.x & 31;
    const __nv_bfloat16* rh = hh + (size_t)gw * NHID;
    const __nv_bfloat16* rl = hl + (size_t)gw * NHID;
    float s = 0.f;
    #pragma unroll
    for (int it = 0; it < NHID/256; it++){
        const int k = it*256 + lane*8;
        uint4 hv = *(const uint4*)(rh + k);
        uint4 lv = *(const uint4*)(rl + k);
        const __nv_bfloat162* hp = (const __nv_bfloat162*)&hv;
        const __nv_bfloat162* lp = (const __nv_bfloat162*)&lv;
        float4 wa = *(const float4*)(w2 + k);
        float4 wb = *(const float4*)(w2 + k + 4);
        float2 f0 = __bfloat1622float2(hp[0]), g0 = __bfloat1622float2(lp[0]);
        float2 f1 = __bfloat1622float2(hp[1]), g1 = __bfloat1622float2(lp[1]);
        float2 f2 = __bfloat1622float2(hp[2]), g2 = __bfloat1622float2(lp[2]);
        float2 f3 = __bfloat1622float2(hp[3]), g3 = __bfloat1622float2(lp[3]);
        s += (f0.x+g0.x)*wa.x + (f0.y+g0.y)*wa.y + (f1.x+g1.x)*wa.z + (f1.y+g1.y)*wa.w
           + (f2.x+g2.x)*wb.x + (f2.y+g2.y)*wb.y + (f3.x+g3.x)*wb.z + (f3.y+g3.y)*wb.w;
    }
    #pragma unroll
    for (int o = 16; o; o >>= 1) s += __shfl_xor_sync(0xffffffffu, s, o);
    if (lane == 0){
        const float z = s + b2[0];
        const float o = 1.f / (1.f + __expf(-z));
        out[gw] = o;
        float alpha;
        if      (o <= 0.2f) alpha = 0.1f - 0.5f*o;
        else if (o >= 0.8f) alpha = 0.5f*o - 0.4f;
        else                alpha = 0.f;
        out[BATCH + gw] = alpha;
    }
}

extern "C" void kernel_launch(void* const* d_in, const int* in_sizes, int n_in,
                              void* d_out, int out_size)
{
    const float* x  = (const float*)d_in[0];
    const float* W0 = (const float*)d_in[1];
    const float* b0 = (const float*)d_in[2];
    const float* W1 = (const float*)d_in[3];
    const float* b1 = (const float*)d_in[4];
    const float* W2 = (const float*)d_in[5];
    const float* b2 = (const float*)d_in[6];
    float* out = (float*)d_out;

    __nv_bfloat16 *xh,*xl,*w0h,*w0l,*w1h,*w1l,*h0h,*h0l,*h1h,*h1l;
    cudaGetSymbolAddress((void**)&xh,  g_xh);  cudaGetSymbolAddress((void**)&xl,  g_xl);
    cudaGetSymbolAddress((void**)&w0h, g_w0h); cudaGetSymbolAddress((void**)&w0l, g_w0l);
    cudaGetSymbolAddress((void**)&w1h, g_w1h); cudaGetSymbolAddress((void**)&w1l, g_w1l);
    cudaGetSymbolAddress((void**)&h0h, g_h0h); cudaGetSymbolAddress((void**)&h0l, g_h0l);
    cudaGetSymbolAddress((void**)&h1h, g_h1h); cudaGetSymbolAddress((void**)&h1l, g_h1l);

    cudaFuncSetAttribute(gemm_split, cudaFuncAttributeMaxDynamicSharedMemorySize, SMEM_SZ);

    cvt_x_k<<<(BATCH*NIN/4)/256, 256>>>(x, xh, xl);
    tr_cvt_k<<<dim3(NHID/32, NIN/32),  dim3(32,8)>>>(W0, w0h, w0l, NIN,  NHID);
    tr_cvt_k<<<dim3(NHID/32, NHID/32), dim3(32,8)>>>(W1, w1h, w1l, NHID, NHID);

    gemm_split<<<dim3(NHID/BN, BATCH/BM), 512, SMEM_SZ>>>(
        xh, xl, w0h, w0l, b0, h0h, h0l, BATCH, NHID, NIN);
    gemm_split<<<dim3(NHID/BN, BATCH/BM), 512, SMEM_SZ>>>(
        h0h, h0l, w1h, w1l, b1, h1h, h1l, BATCH, NHID, NHID);

    final_k<<<BATCH/8, 256>>>(h1h, h1l, W2, b2, out);
}

// round 10
// speedup vs baseline: 1.0531x; 1.0531x over previous
#include <cuda_runtime.h>
#include <cuda_bf16.h>
#include <stdint.h>

#define BATCH 32768
#define NIN   1024
#define NHID  2048

// ---- scratch (static __device__, no allocation) ----
__device__ __align__(256) __nv_bfloat16 g_xh [(size_t)BATCH*NIN];
__device__ __align__(256) __nv_bfloat16 g_xl [(size_t)BATCH*NIN];
__device__ __align__(256) __nv_bfloat16 g_w0h[(size_t)NHID*NIN];    // [n][k]
__device__ __align__(256) __nv_bfloat16 g_w0l[(size_t)NHID*NIN];
__device__ __align__(256) __nv_bfloat16 g_w1h[(size_t)NHID*NHID];
__device__ __align__(256) __nv_bfloat16 g_w1l[(size_t)NHID*NHID];
__device__ __align__(256) __nv_bfloat16 g_h0h[(size_t)BATCH*NHID];
__device__ __align__(256) __nv_bfloat16 g_h0l[(size_t)BATCH*NHID];
__device__ __align__(256) __nv_bfloat16 g_h1h[(size_t)BATCH*NHID];
__device__ __align__(256) __nv_bfloat16 g_h1l[(size_t)BATCH*NHID];

// ---- helpers ----
__device__ __forceinline__ uint32_t s2u(const void* p){
    return (uint32_t)__cvta_generic_to_shared(p);
}
__device__ __forceinline__ void cp16(uint32_t d, const void* s){
    asm volatile("cp.async.cg.shared.global [%0], [%1], 16;\n" :: "r"(d), "l"(s));
}
__device__ __forceinline__ void ldm4(uint32_t&r0,uint32_t&r1,uint32_t&r2,uint32_t&r3,uint32_t a){
    asm volatile("ldmatrix.sync.aligned.m8n8.x4.shared.b16 {%0,%1,%2,%3},[%4];\n"
        : "=r"(r0),"=r"(r1),"=r"(r2),"=r"(r3) : "r"(a));
}
__device__ __forceinline__ void mma16816(float* c, const uint32_t* a, const uint32_t* b){
    asm volatile("mma.sync.aligned.m16n8k16.row.col.f32.bf16.bf16.f32 "
        "{%0,%1,%2,%3},{%4,%5,%6,%7},{%8,%9},{%0,%1,%2,%3};\n"
        : "+f"(c[0]),"+f"(c[1]),"+f"(c[2]),"+f"(c[3])
        : "r"(a[0]),"r"(a[1]),"r"(a[2]),"r"(a[3]),"r"(b[0]),"r"(b[1]));
}
__device__ __forceinline__ float eluf(float x){ return x > 0.f ? x : (__expf(x) - 1.f); }
__device__ __forceinline__ void split_bf16(float v, __nv_bfloat16& h, __nv_bfloat16& l){
    h = __float2bfloat16(v);
    l = __float2bfloat16(v - __bfloat162float(h));
}

// ---- tile geometry: BM=256 x BN=128, 16 warps of 64x32 ----
#define BM 256
#define BN 128
#define BK 32
#define ROWB 80                 // 64B data + 16B pad -> conflict-free ldmatrix
#define A_PLANE (256*80)        // 20480
#define B_PLANE (128*80)        // 10240
#define STAGEB  (2*A_PLANE + 2*B_PLANE)   // 61440
#define NSTAGE 3
#define SMEM_SZ (NSTAGE*STAGEB) // 184320
#define P_AH 0u
#define P_AL 20480u
#define P_BH 40960u
#define P_BL 51200u

// C = elu(A @ BT^T + bias); split-bf16 hi/lo planes; fp32 accum.
// 512 threads, 16 warps (4x4 grid of 64x32 tiles), 3-stage cp.async pipeline,
// single fragment buffer, term-major mma (acc reuse dist = 16).
__global__ void __launch_bounds__(512,1)
gemm_split(const __nv_bfloat16* __restrict__ Ah, const __nv_bfloat16* __restrict__ Al,
           const __nv_bfloat16* __restrict__ Bh, const __nv_bfloat16* __restrict__ Bl,
           const float* __restrict__ bias,
           __nv_bfloat16* __restrict__ Ch, __nv_bfloat16* __restrict__ Cl,
           int M, int N, int K)
{
    extern __shared__ __align__(16) unsigned char sm[];
    const uint32_t sb = s2u(sm);
    const int tid = threadIdx.x;
    const int m0 = blockIdx.y * BM;
    const int n0 = blockIdx.x * BN;
    const int KT = K / BK;

    // A: 256 rows x 4 chunks = 1024 slots (2/thread); B: 128x4 = 512 (1/thread)
    const int arow0 = tid >> 2;            // 0..127
    const int ac    = tid & 3;
    const int brow  = tid >> 2;            // reuse, 0..127
    auto load = [&](int kt, int st){
        const int kk = kt * BK;
        const uint32_t s0 = sb + (uint32_t)st*STAGEB;
        #pragma unroll
        for (int i = 0; i < 2; i++){
            const int row = arow0 + i*128;
            const uint32_t dso = (uint32_t)(row*ROWB + ac*16);
            const size_t ao = (size_t)(m0+row)*K + kk + ac*8;
            cp16(s0 + P_AH + dso, Ah + ao);
            cp16(s0 + P_AL + dso, Al + ao);
        }
        {
            const uint32_t dso = (uint32_t)(brow*ROWB + ac*16);
            const size_t bo = (size_t)(n0+brow)*K + kk + ac*8;
            cp16(s0 + P_BH + dso, Bh + bo);
            cp16(s0 + P_BL + dso, Bl + bo);
        }
        asm volatile("cp.async.commit_group;\n" ::: "memory");
    };

    const int warp = tid >> 5, lane = tid & 31;
    const int wr = warp >> 2, wc = warp & 3;   // 4x4 grid of 64x32 warp tiles

    const int a_row  = wr*64 + (lane & 15);
    const int a_colb = (lane >> 4) * 16;
    const int b_row  = wc*32 + (lane >> 4)*8 + (lane & 7);
    const int b_colb = ((lane >> 3) & 1) * 16;

    float acc[4][4][4];
    #pragma unroll
    for (int i=0;i<4;i++)
        #pragma unroll
        for (int j=0;j<4;j++)
            #pragma unroll
            for (int k=0;k<4;k++) acc[i][j][k] = 0.f;

    load(0, 0);
    load(1, 1);

    for (int kt = 0; kt < KT; kt++){
        if (kt < KT-1) asm volatile("cp.async.wait_group 1;\n" ::: "memory");
        else           asm volatile("cp.async.wait_group 0;\n" ::: "memory");
        __syncthreads();
        if (kt + 2 < KT) load(kt + 2, (kt + 2) % NSTAGE);

        const uint32_t s0 = sb + (uint32_t)((kt % NSTAGE)*STAGEB);

        #pragma unroll
        for (int ks = 0; ks < 2; ks++){
            uint32_t ah[4][4], al[4][4];
            #pragma unroll
            for (int i = 0; i < 4; i++){
                const uint32_t ro = (uint32_t)(a_row + i*16)*ROWB + a_colb + ks*32;
                ldm4(ah[i][0],ah[i][1],ah[i][2],ah[i][3], s0 + P_AH + ro);
                ldm4(al[i][0],al[i][1],al[i][2],al[i][3], s0 + P_AL + ro);
            }
            uint32_t bh[4][2], bl[4][2];
            #pragma unroll
            for (int p = 0; p < 2; p++){
                const uint32_t ro = (uint32_t)(b_row + p*16)*ROWB + b_colb + ks*32;
                uint32_t r0,r1,r2,r3;
                ldm4(r0,r1,r2,r3, s0 + P_BH + ro);
                bh[p*2][0]=r0; bh[p*2][1]=r1; bh[p*2+1][0]=r2; bh[p*2+1][1]=r3;
                ldm4(r0,r1,r2,r3, s0 + P_BL + ro);
                bl[p*2][0]=r0; bl[p*2][1]=r1; bl[p*2+1][0]=r2; bl[p*2+1][1]=r3;
            }
            // term-major: same-acc mmas 16 apart -> RAW fully hidden
            #pragma unroll
            for (int t = 0; t < 3; t++){
                const uint32_t (*fa)[4] = (t == 2) ? al : ah;
                const uint32_t (*fb)[2] = (t == 1) ? bl : bh;
                #pragma unroll
                for (int i = 0; i < 4; i++)
                    #pragma unroll
                    for (int j = 0; j < 4; j++)
                        mma16816(acc[i][j], fa[i], fb[j]);
            }
        }
    }

    // epilogue: bias + elu -> hi/lo bf16 planes
    const int gid = lane >> 2, tig = lane & 3;
    #pragma unroll
    for (int i = 0; i < 4; i++){
        const int mrow = m0 + wr*64 + i*16 + gid;
        #pragma unroll
        for (int j = 0; j < 4; j++){
            const int n = n0 + wc*32 + j*8 + tig*2;
            const float2 bv = *(const float2*)&bias[n];
            float v[4] = {acc[i][j][0] + bv.x, acc[i][j][1] + bv.y,
                          acc[i][j][2] + bv.x, acc[i][j][3] + bv.y};
            v[0]=eluf(v[0]); v[1]=eluf(v[1]); v[2]=eluf(v[2]); v[3]=eluf(v[3]);
            __nv_bfloat16 h[4], l[4];
            #pragma unroll
            for (int q = 0; q < 4; q++) split_bf16(v[q], h[q], l[q]);
            const size_t o0 = (size_t)mrow*N + n, o1 = (size_t)(mrow+8)*N + n;
            *(__nv_bfloat162*)&Ch[o0] = *(__nv_bfloat162*)&h[0];
            *(__nv_bfloat162*)&Cl[o0] = *(__nv_bfloat162*)&l[0];
            *(__nv_bfloat162*)&Ch[o1] = *(__nv_bfloat162*)&h[2];
            *(__nv_bfloat162*)&Cl[o1] = *(__nv_bfloat162*)&l[2];
        }
    }
}

// fp32 x -> hi/lo bf16 planes
__global__ void cvt_x_k(const float* __restrict__ x,
                        __nv_bfloat16* __restrict__ xh, __nv_bfloat16* __restrict__ xl){
    size_t i = (size_t)blockIdx.x * blockDim.x + threadIdx.x;
    float4 v = ((const float4*)x)[i];
    __nv_bfloat16 h[4], l[4];
    split_bf16(v.x, h[0], l[0]); split_bf16(v.y, h[1], l[1]);
    split_bf16(v.z, h[2], l[2]); split_bf16(v.w, h[3], l[3]);
    ((uint2*)xh)[i] = *(uint2*)h;
    ((uint2*)xl)[i] = *(uint2*)l;
}

// w[k][n] fp32 -> wt hi/lo [n][k] bf16
__global__ void tr_cvt_k(const float* __restrict__ w,
                         __nv_bfloat16* __restrict__ wth, __nv_bfloat16* __restrict__ wtl,
                         int K, int N){
    __shared__ float t[32][33];
    const int n0 = blockIdx.x*32, k0 = blockIdx.y*32;
    #pragma unroll
    for (int r = threadIdx.y; r < 32; r += 8)
        t[r][threadIdx.x] = w[(size_t)(k0+r)*N + n0 + threadIdx.x];
    __syncthreads();
    #pragma unroll
    for (int r = threadIdx.y; r < 32; r += 8){
        float v = t[threadIdx.x][r];
        __nv_bfloat16 h, l; split_bf16(v, h, l);
        const size_t o = (size_t)(n0+r)*K + k0 + threadIdx.x;
        wth[o] = h; wtl[o] = l;
    }
}

// layer 3: warp-per-row matvec (hi+lo reconstruct) + sigmoid + alpha
__global__ void final_k(const __nv_bfloat16* __restrict__ hh, const __nv_bfloat16* __restrict__ hl,
                        const float* __restrict__ w2, const float* __restrict__ b2,
                        float* __restrict__ out){
    const int gw   = (blockIdx.x*blockDim.x + threadIdx.x) >> 5;
    const int lane = threadIdx.x & 31;
    const __nv_bfloat16* rh = hh + (size_t)gw * NHID;
    const __nv_bfloat16* rl = hl + (size_t)gw * NHID;
    float s = 0.f;
    #pragma unroll
    for (int it = 0; it < NHID/256; it++){
        const int k = it*256 + lane*8;
        uint4 hv = *(const uint4*)(rh + k);
        uint4 lv = *(const uint4*)(rl + k);
        const __nv_bfloat162* hp = (const __nv_bfloat162*)&hv;
        const __nv_bfloat162* lp = (const __nv_bfloat162*)&lv;
        float4 wa = *(const float4*)(w2 + k);
        float4 wb = *(const float4*)(w2 + k + 4);
        float2 f0 = __bfloat1622float2(hp[0]), g0 = __bfloat1622float2(lp[0]);
        float2 f1 = __bfloat1622float2(hp[1]), g1 = __bfloat1622float2(lp[1]);
        float2 f2 = __bfloat1622float2(hp[2]), g2 = __bfloat1622float2(lp[2]);
        float2 f3 = __bfloat1622float2(hp[3]), g3 = __bfloat1622float2(lp[3]);
        s += (f0.x+g0.x)*wa.x + (f0.y+g0.y)*wa.y + (f1.x+g1.x)*wa.z + (f1.y+g1.y)*wa.w
           + (f2.x+g2.x)*wb.x + (f2.y+g2.y)*wb.y + (f3.x+g3.x)*wb.z + (f3.y+g3.y)*wb.w;
    }
    #pragma unroll
    for (int o = 16; o; o >>= 1) s += __shfl_xor_sync(0xffffffffu, s, o);
    if (lane == 0){
        const float z = s + b2[0];
        const float o = 1.f / (1.f + __expf(-z));
        out[gw] = o;
        float alpha;
        if      (o <= 0.2f) alpha = 0.1f - 0.5f*o;
        else if (o >= 0.8f) alpha = 0.5f*o - 0.4f;
        else                alpha = 0.f;
        out[BATCH + gw] = alpha;
    }
}

extern "C" void kernel_launch(void* const* d_in, const int* in_sizes, int n_in,
                              void* d_out, int out_size)
{
    const float* x  = (const float*)d_in[0];
    const float* W0 = (const float*)d_in[1];
    const float* b0 = (const float*)d_in[2];
    const float* W1 = (const float*)d_in[3];
    const float* b1 = (const float*)d_in[4];
    const float* W2 = (const float*)d_in[5];
    const float* b2 = (const float*)d_in[6];
    float* out = (float*)d_out;

    __nv_bfloat16 *xh,*xl,*w0h,*w0l,*w1h,*w1l,*h0h,*h0l,*h1h,*h1l;
    cudaGetSymbolAddress((void**)&xh,  g_xh);  cudaGetSymbolAddress((void**)&xl,  g_xl);
    cudaGetSymbolAddress((void**)&w0h, g_w0h); cudaGetSymbolAddress((void**)&w0l, g_w0l);
    cudaGetSymbolAddress((void**)&w1h, g_w1h); cudaGetSymbolAddress((void**)&w1l, g_w1l);
    cudaGetSymbolAddress((void**)&h0h, g_h0h); cudaGetSymbolAddress((void**)&h0l, g_h0l);
    cudaGetSymbolAddress((void**)&h1h, g_h1h); cudaGetSymbolAddress((void**)&h1l, g_h1l);

    cudaFuncSetAttribute(gemm_split, cudaFuncAttributeMaxDynamicSharedMemorySize, SMEM_SZ);

    cvt_x_k<<<(BATCH*NIN/4)/256, 256>>>(x, xh, xl);
    tr_cvt_k<<<dim3(NHID/32, NIN/32),  dim3(32,8)>>>(W0, w0h, w0l, NIN,  NHID);
    tr_cvt_k<<<dim3(NHID/32, NHID/32), dim3(32,8)>>>(W1, w1h, w1l, NHID, NHID);

    gemm_split<<<dim3(NHID/BN, BATCH/BM), 512, SMEM_SZ>>>(
        xh, xl, w0h, w0l, b0, h0h, h0l, BATCH, NHID, NIN);
    gemm_split<<<dim3(NHID/BN, BATCH/BM), 512, SMEM_SZ>>>(
        h0h, h0l, w1h, w1l, b1, h1h, h1l, BATCH, NHID, NHID);

    final_k<<<BATCH/8, 256>>>(h1h, h1l, W2, b2, out);
}

// round 12
// speedup vs baseline: 1.2226x; 1.1609x over previous
#include <cuda_runtime.h>
#include <cuda_bf16.h>
#include <stdint.h>

#define BATCH 32768
#define NIN   1024
#define NHID  2048

// ---- scratch (static __device__, no allocation) ----
__device__ __align__(256) __nv_bfloat16 g_xh [(size_t)BATCH*NIN];
__device__ __align__(256) __nv_bfloat16 g_xl [(size_t)BATCH*NIN];
__device__ __align__(256) __nv_bfloat16 g_w0h[(size_t)NHID*NIN];    // [n][k]
__device__ __align__(256) __nv_bfloat16 g_w0l[(size_t)NHID*NIN];
__device__ __align__(256) __nv_bfloat16 g_w1h[(size_t)NHID*NHID];
__device__ __align__(256) __nv_bfloat16 g_w1l[(size_t)NHID*NHID];
__device__ __align__(256) __nv_bfloat16 g_h0h[(size_t)BATCH*NHID];
__device__ __align__(256) __nv_bfloat16 g_h0l[(size_t)BATCH*NHID];
__device__ __align__(256) __nv_bfloat16 g_h1h[(size_t)BATCH*NHID];
__device__ __align__(256) __nv_bfloat16 g_h1l[(size_t)BATCH*NHID];

// ---- helpers ----
__device__ __forceinline__ uint32_t s2u(const void* p){
    return (uint32_t)__cvta_generic_to_shared(p);
}
__device__ __forceinline__ void cp16(uint32_t d, const void* s){
    asm volatile("cp.async.cg.shared.global [%0], [%1], 16;\n" :: "r"(d), "l"(s));
}
__device__ __forceinline__ void ldm4(uint32_t&r0,uint32_t&r1,uint32_t&r2,uint32_t&r3,uint32_t a){
    asm volatile("ldmatrix.sync.aligned.m8n8.x4.shared.b16 {%0,%1,%2,%3},[%4];\n"
        : "=r"(r0),"=r"(r1),"=r"(r2),"=r"(r3) : "r"(a));
}
__device__ __forceinline__ void mma16816(float* c, const uint32_t* a, const uint32_t* b){
    asm volatile("mma.sync.aligned.m16n8k16.row.col.f32.bf16.bf16.f32 "
        "{%0,%1,%2,%3},{%4,%5,%6,%7},{%8,%9},{%0,%1,%2,%3};\n"
        : "+f"(c[0]),"+f"(c[1]),"+f"(c[2]),"+f"(c[3])
        : "r"(a[0]),"r"(a[1]),"r"(a[2]),"r"(a[3]),"r"(b[0]),"r"(b[1]));
}
__device__ __forceinline__ float eluf(float x){ return x > 0.f ? x : (__expf(x) - 1.f); }
__device__ __forceinline__ void split_bf16(float v, __nv_bfloat16& h, __nv_bfloat16& l){
    h = __float2bfloat16(v);
    l = __float2bfloat16(v - __bfloat162float(h));
}

// ---- tile geometry: BM=128 x BN=64, 8 warps (4x2) of 32x32, 2 CTAs/SM ----
#define BM 128
#define BN 64
#define BK 32
#define ROWB 80                   // 64B data + 16B pad -> conflict-free ldmatrix
#define A_PLANE (128*80)          // 10240
#define B_PLANE (64*80)           // 5120
#define STAGEB  (2*A_PLANE + 2*B_PLANE)   // 30720
#define NSTAGE 3
#define SMEM_SZ (NSTAGE*STAGEB)   // 92160/CTA -> 184320 for 2 CTAs
#define P_AH 0u
#define P_AL 10240u
#define P_BH 20480u
#define P_BL 25600u

// fragment set for one ks half-chunk
struct Frag {
    uint32_t ah[2][4], al[2][4];
    uint32_t bh[4][2], bl[4][2];
};

// C = elu(A @ BT^T + bias); split-bf16 hi/lo planes; fp32 accum.
// 256 threads, 8 warps (4x2, 32x32 warp tiles), 3-stage cp.async pipeline,
// register double-buffered fragments, term-major mma, 2 independent CTAs/SM.
__global__ void __launch_bounds__(256,2)
gemm_split(const __nv_bfloat16* __restrict__ Ah, const __nv_bfloat16* __restrict__ Al,
           const __nv_bfloat16* __restrict__ Bh, const __nv_bfloat16* __restrict__ Bl,
           const float* __restrict__ bias,
           __nv_bfloat16* __restrict__ Ch, __nv_bfloat16* __restrict__ Cl,
           int M, int N, int K)
{
    extern __shared__ __align__(16) unsigned char sm[];
    const uint32_t sb = s2u(sm);
    const int tid = threadIdx.x;
    const int m0 = blockIdx.y * BM;
    const int n0 = blockIdx.x * BN;
    const int KT = K / BK;

    // A: 128 rows x 4 chunks = 512 slots (2/thread); B: 64 rows x 4 = 256 (1/thread)
    const int ac = tid & 3;
    auto load = [&](int kt, int st){
        const int kk = kt * BK;
        const uint32_t s0 = sb + (uint32_t)st*STAGEB;
        #pragma unroll
        for (int i = 0; i < 2; i++){
            const int row = (tid >> 2) + i*64;     // 0..127
            const uint32_t dso = (uint32_t)(row*ROWB + ac*16);
            const size_t ao = (size_t)(m0+row)*K + kk + ac*8;
            cp16(s0 + P_AH + dso, Ah + ao);
            cp16(s0 + P_AL + dso, Al + ao);
        }
        {
            const int br = tid >> 2;               // 0..63
            const uint32_t dso = (uint32_t)(br*ROWB + ac*16);
            const size_t bo = (size_t)(n0+br)*K + kk + ac*8;
            cp16(s0 + P_BH + dso, Bh + bo);
            cp16(s0 + P_BL + dso, Bl + bo);
        }
        asm volatile("cp.async.commit_group;\n" ::: "memory");
    };

    const int warp = tid >> 5, lane = tid & 31;
    const int wr = warp >> 1, wc = warp & 1;   // 4x2 grid of 32x32 tiles

    const int a_row  = wr*32 + (lane & 15);
    const int a_colb = (lane >> 4) * 16;
    const int b_row  = wc*32 + (lane >> 4)*8 + (lane & 7);
    const int b_colb = ((lane >> 3) & 1) * 16;

    auto ldfrags = [&](int st, int ks, Frag& f){
        const uint32_t s0 = sb + (uint32_t)st*STAGEB;
        #pragma unroll
        for (int i = 0; i < 2; i++){
            const uint32_t ro = (uint32_t)(a_row + i*16)*ROWB + a_colb + ks*32;
            ldm4(f.ah[i][0],f.ah[i][1],f.ah[i][2],f.ah[i][3], s0 + P_AH + ro);
            ldm4(f.al[i][0],f.al[i][1],f.al[i][2],f.al[i][3], s0 + P_AL + ro);
        }
        #pragma unroll
        for (int p = 0; p < 2; p++){
            const uint32_t ro = (uint32_t)(b_row + p*16)*ROWB + b_colb + ks*32;
            uint32_t r0,r1,r2,r3;
            ldm4(r0,r1,r2,r3, s0 + P_BH + ro);
            f.bh[p*2][0]=r0; f.bh[p*2][1]=r1; f.bh[p*2+1][0]=r2; f.bh[p*2+1][1]=r3;
            ldm4(r0,r1,r2,r3, s0 + P_BL + ro);
            f.bl[p*2][0]=r0; f.bl[p*2][1]=r1; f.bl[p*2+1][0]=r2; f.bl[p*2+1][1]=r3;
        }
    };

    float acc[2][4][4];
    #pragma unroll
    for (int i=0;i<2;i++)
        #pragma unroll
        for (int j=0;j<4;j++)
            #pragma unroll
            for (int k=0;k<4;k++) acc[i][j][k] = 0.f;

    // term-major: same-acc mmas are 8 apart -> HMMA RAW latency hidden
    auto mma3 = [&](const Frag& f){
        #pragma unroll
        for (int t = 0; t < 3; t++){
            const uint32_t (*fa)[4] = (t == 2) ? f.al : f.ah;
            const uint32_t (*fb)[2] = (t == 1) ? f.bl : f.bh;
            #pragma unroll
            for (int i = 0; i < 2; i++)
                #pragma unroll
                for (int j = 0; j < 4; j++)
                    mma16816(acc[i][j], fa[i], fb[j]);
        }
    };

    load(0, 0);
    load(1, 1);
    asm volatile("cp.async.wait_group 1;\n" ::: "memory");
    __syncthreads();

    Frag F0, F1;
    ldfrags(0, 0, F0);

    for (int kt = 0; kt < KT; kt++){
        const int st = kt % NSTAGE;
        ldfrags(st, 1, F1);          // LDSM for ks=1 in flight during...
        mma3(F0);                    // ...this mma burst
        if (kt + 2 < KT) load(kt + 2, (kt + 2) % NSTAGE);
        if (kt + 1 < KT){
            if (kt + 2 < KT) asm volatile("cp.async.wait_group 1;\n" ::: "memory");
            else             asm volatile("cp.async.wait_group 0;\n" ::: "memory");
            __syncthreads();
            ldfrags((kt + 1) % NSTAGE, 0, F0);
        }
        mma3(F1);
    }

    // epilogue: bias + elu -> hi/lo bf16 planes
    const int gid = lane >> 2, tig = lane & 3;
    #pragma unroll
    for (int i = 0; i < 2; i++){
        const int mrow = m0 + wr*32 + i*16 + gid;
        #pragma unroll
        for (int j = 0; j < 4; j++){
            const int n = n0 + wc*32 + j*8 + tig*2;
            const float2 bv = *(const float2*)&bias[n];
            float v[4] = {acc[i][j][0] + bv.x, acc[i][j][1] + bv.y,
                          acc[i][j][2] + bv.x, acc[i][j][3] + bv.y};
            v[0]=eluf(v[0]); v[1]=eluf(v[1]); v[2]=eluf(v[2]); v[3]=eluf(v[3]);
            __nv_bfloat16 h[4], l[4];
            #pragma unroll
            for (int q = 0; q < 4; q++) split_bf16(v[q], h[q], l[q]);
            const size_t o0 = (size_t)mrow*N + n, o1 = (size_t)(mrow+8)*N + n;
            *(__nv_bfloat162*)&Ch[o0] = *(__nv_bfloat162*)&h[0];
            *(__nv_bfloat162*)&Cl[o0] = *(__nv_bfloat162*)&l[0];
            *(__nv_bfloat162*)&Ch[o1] = *(__nv_bfloat162*)&h[2];
            *(__nv_bfloat162*)&Cl[o1] = *(__nv_bfloat162*)&l[2];
        }
    }
}

// fp32 x -> hi/lo bf16 planes
__global__ void cvt_x_k(const float* __restrict__ x,
                        __nv_bfloat16* __restrict__ xh, __nv_bfloat16* __restrict__ xl){
    size_t i = (size_t)blockIdx.x * blockDim.x + threadIdx.x;
    float4 v = ((const float4*)x)[i];
    __nv_bfloat16 h[4], l[4];
    split_bf16(v.x, h[0], l[0]); split_bf16(v.y, h[1], l[1]);
    split_bf16(v.z, h[2], l[2]); split_bf16(v.w, h[3], l[3]);
    ((uint2*)xh)[i] = *(uint2*)h;
    ((uint2*)xl)[i] = *(uint2*)l;
}

// w[k][n] fp32 -> wt hi/lo [n][k] bf16
__global__ void tr_cvt_k(const float* __restrict__ w,
                         __nv_bfloat16* __restrict__ wth, __nv_bfloat16* __restrict__ wtl,
                         int K, int N){
    __shared__ float t[32][33];
    const int n0 = blockIdx.x*32, k0 = blockIdx.y*32;
    #pragma unroll
    for (int r = threadIdx.y; r < 32; r += 8)
        t[r][threadIdx.x] = w[(size_t)(k0+r)*N + n0 + threadIdx.x];
    __syncthreads();
    #pragma unroll
    for (int r = threadIdx.y; r < 32; r += 8){
        float v = t[threadIdx.x][r];
        __nv_bfloat16 h, l; split_bf16(v, h, l);
        const size_t o = (size_t)(n0+r)*K + k0 + threadIdx.x;
        wth[o] = h; wtl[o] = l;
    }
}

// layer 3: warp-per-row matvec (hi+lo reconstruct) + sigmoid + alpha
__global__ void final_k(const __nv_bfloat16* __restrict__ hh, const __nv_bfloat16* __restrict__ hl,
                        const float* __restrict__ w2, const float* __restrict__ b2,
                        float* __restrict__ out){
    const int gw   = (blockIdx.x*blockDim.x + threadIdx.x) >> 5;
    const int lane = threadIdx.x & 31;
    const __nv_bfloat16* rh = hh + (size_t)gw * NHID;
    const __nv_bfloat16* rl = hl + (size_t)gw * NHID;
    float s = 0.f;
    #pragma unroll
    for (int it = 0; it < NHID/256; it++){
        const int k = it*256 + lane*8;
        uint4 hv = *(const uint4*)(rh + k);
        uint4 lv = *(const uint4*)(rl + k);
        const __nv_bfloat162* hp = (const __nv_bfloat162*)&hv;
        const __nv_bfloat162* lp = (const __nv_bfloat162*)&lv;
        float4 wa = *(const float4*)(w2 + k);
        float4 wb = *(const float4*)(w2 + k + 4);
        float2 f0 = __bfloat1622float2(hp[0]), g0 = __bfloat1622float2(lp[0]);
        float2 f1 = __bfloat1622float2(hp[1]), g1 = __bfloat1622float2(lp[1]);
        float2 f2 = __bfloat1622float2(hp[2]), g2 = __bfloat1622float2(lp[2]);
        float2 f3 = __bfloat1622float2(hp[3]), g3 = __bfloat1622float2(lp[3]);
        s += (f0.x+g0.x)*wa.x + (f0.y+g0.y)*wa.y + (f1.x+g1.x)*wa.z + (f1.y+g1.y)*wa.w
           + (f2.x+g2.x)*wb.x + (f2.y+g2.y)*wb.y + (f3.x+g3.x)*wb.z + (f3.y+g3.y)*wb.w;
    }
    #pragma unroll
    for (int o = 16; o; o >>= 1) s += __shfl_xor_sync(0xffffffffu, s, o);
    if (lane == 0){
        const float z = s + b2[0];
        const float o = 1.f / (1.f + __expf(-z));
        out[gw] = o;
        float alpha;
        if      (o <= 0.2f) alpha = 0.1f - 0.5f*o;
        else if (o >= 0.8f) alpha = 0.5f*o - 0.4f;
        else                alpha = 0.f;
        out[BATCH + gw] = alpha;
    }
}

extern "C" void kernel_launch(void* const* d_in, const int* in_sizes, int n_in,
                              void* d_out, int out_size)
{
    const float* x  = (const float*)d_in[0];
    const float* W0 = (const float*)d_in[1];
    const float* b0 = (const float*)d_in[2];
    const float* W1 = (const float*)d_in[3];
    const float* b1 = (const float*)d_in[4];
    const float* W2 = (const float*)d_in[5];
    const float* b2 = (const float*)d_in[6];
    float* out = (float*)d_out;

    __nv_bfloat16 *xh,*xl,*w0h,*w0l,*w1h,*w1l,*h0h,*h0l,*h1h,*h1l;
    cudaGetSymbolAddress((void**)&xh,  g_xh);  cudaGetSymbolAddress((void**)&xl,  g_xl);
    cudaGetSymbolAddress((void**)&w0h, g_w0h); cudaGetSymbolAddress((void**)&w0l, g_w0l);
    cudaGetSymbolAddress((void**)&w1h, g_w1h); cudaGetSymbolAddress((void**)&w1l, g_w1l);
    cudaGetSymbolAddress((void**)&h0h, g_h0h); cudaGetSymbolAddress((void**)&h0l, g_h0l);
    cudaGetSymbolAddress((void**)&h1h, g_h1h); cudaGetSymbolAddress((void**)&h1l, g_h1l);

    cudaFuncSetAttribute(gemm_split, cudaFuncAttributeMaxDynamicSharedMemorySize, SMEM_SZ);

    cvt_x_k<<<(BATCH*NIN/4)/256, 256>>>(x, xh, xl);
    tr_cvt_k<<<dim3(NHID/32, NIN/32),  dim3(32,8)>>>(W0, w0h, w0l, NIN,  NHID);
    tr_cvt_k<<<dim3(NHID/32, NHID/32), dim3(32,8)>>>(W1, w1h, w1l, NHID, NHID);

    gemm_split<<<dim3(NHID/BN, BATCH/BM), 256, SMEM_SZ>>>(
        xh, xl, w0h, w0l, b0, h0h, h0l, BATCH, NHID, NIN);
    gemm_split<<<dim3(NHID/BN, BATCH/BM), 256, SMEM_SZ>>>(
        h0h, h0l, w1h, w1l, b1, h1h, h1l, BATCH, NHID, NHID);

    final_k<<<BATCH/8, 256>>>(h1h, h1l, W2, b2, out);
}

// round 13
// speedup vs baseline: 1.5266x; 1.2487x over previous
#include <cuda_runtime.h>
#include <cuda_fp16.h>
#include <stdint.h>

#define BATCH 32768
#define NIN   1024
#define NHID  2048

// ---- scratch (static __device__, no allocation) ----
__device__ __align__(256) __half g_xh [(size_t)BATCH*NIN];
__device__ __align__(256) __half g_xl [(size_t)BATCH*NIN];
__device__ __align__(256) __half g_w0 [(size_t)NHID*NIN];    // [n][k] fp16
__device__ __align__(256) __half g_w1 [(size_t)NHID*NHID];
__device__ __align__(256) __half g_h0h[(size_t)BATCH*NHID];
__device__ __align__(256) __half g_h0l[(size_t)BATCH*NHID];
__device__ __align__(256) __half g_h1h[(size_t)BATCH*NHID];
__device__ __align__(256) __half g_h1l[(size_t)BATCH*NHID];

// ---- helpers ----
__device__ __forceinline__ uint32_t s2u(const void* p){
    return (uint32_t)__cvta_generic_to_shared(p);
}
__device__ __forceinline__ void cp16(uint32_t d, const void* s){
    asm volatile("cp.async.cg.shared.global [%0], [%1], 16;\n" :: "r"(d), "l"(s));
}
__device__ __forceinline__ void ldm4(uint32_t&r0,uint32_t&r1,uint32_t&r2,uint32_t&r3,uint32_t a){
    asm volatile("ldmatrix.sync.aligned.m8n8.x4.shared.b16 {%0,%1,%2,%3},[%4];\n"
        : "=r"(r0),"=r"(r1),"=r"(r2),"=r"(r3) : "r"(a));
}
__device__ __forceinline__ void mma16816h(float* c, const uint32_t* a, const uint32_t* b){
    asm volatile("mma.sync.aligned.m16n8k16.row.col.f32.f16.f16.f32 "
        "{%0,%1,%2,%3},{%4,%5,%6,%7},{%8,%9},{%0,%1,%2,%3};\n"
        : "+f"(c[0]),"+f"(c[1]),"+f"(c[2]),"+f"(c[3])
        : "r"(a[0]),"r"(a[1]),"r"(a[2]),"r"(a[3]),"r"(b[0]),"r"(b[1]));
}
__device__ __forceinline__ float eluf(float x){ return x > 0.f ? x : (__expf(x) - 1.f); }
__device__ __forceinline__ void split_f16(float v, __half& h, __half& l){
    h = __float2half(v);
    l = __float2half(v - __half2float(h));
}

// ---- tile geometry: BM=128 x BN=64, 8 warps (4x2) of 32x32, 2 CTAs/SM ----
#define BM 128
#define BN 64
#define BK 32
#define ROWB 80                   // 64B data + 16B pad -> conflict-free ldmatrix
#define A_PLANE (128*80)          // 10240
#define B_PLANE (64*80)           // 5120
#define STAGEB  (2*A_PLANE + B_PLANE)   // 25600: Ah, Al, B
#define NSTAGE 3
#define SMEM_SZ (NSTAGE*STAGEB)   // 76800/CTA -> 153600 for 2 CTAs
#define P_AH 0u
#define P_AL 10240u
#define P_B  20480u

// fragment set for one ks half-chunk
struct Frag {
    uint32_t ah[2][4], al[2][4];
    uint32_t b[4][2];
};

// C = elu((Ah+Al) @ W^T + bias); A split fp16 hi/lo, W single fp16; fp32 accum.
// 256 threads, 8 warps (4x2, 32x32 warp tiles), 3-stage cp.async pipeline,
// register double-buffered fragments, term-major mma, 2 independent CTAs/SM.
__global__ void __launch_bounds__(256,2)
gemm_split(const __half* __restrict__ Ah, const __half* __restrict__ Al,
           const __half* __restrict__ Bw,
           const float* __restrict__ bias,
           __half* __restrict__ Ch, __half* __restrict__ Cl,
           int M, int N, int K)
{
    extern __shared__ __align__(16) unsigned char sm[];
    const uint32_t sb = s2u(sm);
    const int tid = threadIdx.x;
    const int m0 = blockIdx.y * BM;
    const int n0 = blockIdx.x * BN;
    const int KT = K / BK;

    // A: 128 rows x 4 chunks = 512 slots (2/thread) per plane; B: 64x4 = 256 (1/thread)
    const int ac = tid & 3;
    auto load = [&](int kt, int st){
        const int kk = kt * BK;
        const uint32_t s0 = sb + (uint32_t)st*STAGEB;
        #pragma unroll
        for (int i = 0; i < 2; i++){
            const int row = (tid >> 2) + i*64;     // 0..127
            const uint32_t dso = (uint32_t)(row*ROWB + ac*16);
            const size_t ao = (size_t)(m0+row)*K + kk + ac*8;
            cp16(s0 + P_AH + dso, Ah + ao);
            cp16(s0 + P_AL + dso, Al + ao);
        }
        {
            const int br = tid >> 2;               // 0..63
            const uint32_t dso = (uint32_t)(br*ROWB + ac*16);
            const size_t bo = (size_t)(n0+br)*K + kk + ac*8;
            cp16(s0 + P_B + dso, Bw + bo);
        }
        asm volatile("cp.async.commit_group;\n" ::: "memory");
    };

    const int warp = tid >> 5, lane = tid & 31;
    const int wr = warp >> 1, wc = warp & 1;   // 4x2 grid of 32x32 tiles

    const int a_row  = wr*32 + (lane & 15);
    const int a_colb = (lane >> 4) * 16;
    const int b_row  = wc*32 + (lane >> 4)*8 + (lane & 7);
    const int b_colb = ((lane >> 3) & 1) * 16;

    auto ldfrags = [&](int st, int ks, Frag& f){
        const uint32_t s0 = sb + (uint32_t)st*STAGEB;
        #pragma unroll
        for (int i = 0; i < 2; i++){
            const uint32_t ro = (uint32_t)(a_row + i*16)*ROWB + a_colb + ks*32;
            ldm4(f.ah[i][0],f.ah[i][1],f.ah[i][2],f.ah[i][3], s0 + P_AH + ro);
            ldm4(f.al[i][0],f.al[i][1],f.al[i][2],f.al[i][3], s0 + P_AL + ro);
        }
        #pragma unroll
        for (int p = 0; p < 2; p++){
            const uint32_t ro = (uint32_t)(b_row + p*16)*ROWB + b_colb + ks*32;
            uint32_t r0,r1,r2,r3;
            ldm4(r0,r1,r2,r3, s0 + P_B + ro);
            f.b[p*2][0]=r0; f.b[p*2][1]=r1; f.b[p*2+1][0]=r2; f.b[p*2+1][1]=r3;
        }
    };

    float acc[2][4][4];
    #pragma unroll
    for (int i=0;i<2;i++)
        #pragma unroll
        for (int j=0;j<4;j++)
            #pragma unroll
            for (int k=0;k<4;k++) acc[i][j][k] = 0.f;

    // term-major: same-acc mmas are 8 apart -> HMMA RAW latency hidden
    auto mma2 = [&](const Frag& f){
        #pragma unroll
        for (int t = 0; t < 2; t++){
            const uint32_t (*fa)[4] = (t == 1) ? f.al : f.ah;
            #pragma unroll
            for (int i = 0; i < 2; i++)
                #pragma unroll
                for (int j = 0; j < 4; j++)
                    mma16816h(acc[i][j], fa[i], f.b[j]);
        }
    };

    load(0, 0);
    load(1, 1);
    asm volatile("cp.async.wait_group 1;\n" ::: "memory");
    __syncthreads();

    Frag F0, F1;
    ldfrags(0, 0, F0);

    for (int kt = 0; kt < KT; kt++){
        const int st = kt % NSTAGE;
        ldfrags(st, 1, F1);          // LDSM for ks=1 in flight during...
        mma2(F0);                    // ...this mma burst
        if (kt + 2 < KT) load(kt + 2, (kt + 2) % NSTAGE);
        if (kt + 1 < KT){
            if (kt + 2 < KT) asm volatile("cp.async.wait_group 1;\n" ::: "memory");
            else             asm volatile("cp.async.wait_group 0;\n" ::: "memory");
            __syncthreads();
            ldfrags((kt + 1) % NSTAGE, 0, F0);
        }
        mma2(F1);
    }

    // epilogue: bias + elu -> hi/lo fp16 planes
    const int gid = lane >> 2, tig = lane & 3;
    #pragma unroll
    for (int i = 0; i < 2; i++){
        const int mrow = m0 + wr*32 + i*16 + gid;
        #pragma unroll
        for (int j = 0; j < 4; j++){
            const int n = n0 + wc*32 + j*8 + tig*2;
            const float2 bv = *(const float2*)&bias[n];
            float v[4] = {acc[i][j][0] + bv.x, acc[i][j][1] + bv.y,
                          acc[i][j][2] + bv.x, acc[i][j][3] + bv.y};
            v[0]=eluf(v[0]); v[1]=eluf(v[1]); v[2]=eluf(v[2]); v[3]=eluf(v[3]);
            __half h[4], l[4];
            #pragma unroll
            for (int q = 0; q < 4; q++) split_f16(v[q], h[q], l[q]);
            const size_t o0 = (size_t)mrow*N + n, o1 = (size_t)(mrow+8)*N + n;
            *(__half2*)&Ch[o0] = *(__half2*)&h[0];
            *(__half2*)&Cl[o0] = *(__half2*)&l[0];
            *(__half2*)&Ch[o1] = *(__half2*)&h[2];
            *(__half2*)&Cl[o1] = *(__half2*)&l[2];
        }
    }
}

// fp32 x -> hi/lo fp16 planes
__global__ void cvt_x_k(const float* __restrict__ x,
                        __half* __restrict__ xh, __half* __restrict__ xl){
    size_t i = (size_t)blockIdx.x * blockDim.x + threadIdx.x;
    float4 v = ((const float4*)x)[i];
    __half h[4], l[4];
    split_f16(v.x, h[0], l[0]); split_f16(v.y, h[1], l[1]);
    split_f16(v.z, h[2], l[2]); split_f16(v.w, h[3], l[3]);
    ((uint2*)xh)[i] = *(uint2*)h;
    ((uint2*)xl)[i] = *(uint2*)l;
}

// w[k][n] fp32 -> wt [n][k] single fp16
__global__ void tr_cvt_k(const float* __restrict__ w,
                         __half* __restrict__ wt, int K, int N){
    __shared__ float t[32][33];
    const int n0 = blockIdx.x*32, k0 = blockIdx.y*32;
    #pragma unroll
    for (int r = threadIdx.y; r < 32; r += 8)
        t[r][threadIdx.x] = w[(size_t)(k0+r)*N + n0 + threadIdx.x];
    __syncthreads();
    #pragma unroll
    for (int r = threadIdx.y; r < 32; r += 8)
        wt[(size_t)(n0+r)*K + k0 + threadIdx.x] = __float2half(t[threadIdx.x][r]);
}

// layer 3: warp-per-row matvec (hi+lo reconstruct) + sigmoid + alpha
__global__ void final_k(const __half* __restrict__ hh, const __half* __restrict__ hl,
                        const float* __restrict__ w2, const float* __restrict__ b2,
                        float* __restrict__ out){
    const int gw   = (blockIdx.x*blockDim.x + threadIdx.x) >> 5;
    const int lane = threadIdx.x & 31;
    const __half* rh = hh + (size_t)gw * NHID;
    const __half* rl = hl + (size_t)gw * NHID;
    float s = 0.f;
    #pragma unroll
    for (int it = 0; it < NHID/256; it++){
        const int k = it*256 + lane*8;
        uint4 hv = *(const uint4*)(rh + k);
        uint4 lv = *(const uint4*)(rl + k);
        const __half2* hp = (const __half2*)&hv;
        const __half2* lp = (const __half2*)&lv;
        float4 wa = *(const float4*)(w2 + k);
        float4 wb = *(const float4*)(w2 + k + 4);
        float2 f0 = __half22float2(hp[0]), g0 = __half22float2(lp[0]);
        float2 f1 = __half22float2(hp[1]), g1 = __half22float2(lp[1]);
        float2 f2 = __half22float2(hp[2]), g2 = __half22float2(lp[2]);
        float2 f3 = __half22float2(hp[3]), g3 = __half22float2(lp[3]);
        s += (f0.x+g0.x)*wa.x + (f0.y+g0.y)*wa.y + (f1.x+g1.x)*wa.z + (f1.y+g1.y)*wa.w
           + (f2.x+g2.x)*wb.x + (f2.y+g2.y)*wb.y + (f3.x+g3.x)*wb.z + (f3.y+g3.y)*wb.w;
    }
    #pragma unroll
    for (int o = 16; o; o >>= 1) s += __shfl_xor_sync(0xffffffffu, s, o);
    if (lane == 0){
        const float z = s + b2[0];
        const float o = 1.f / (1.f + __expf(-z));
        out[gw] = o;
        float alpha;
        if      (o <= 0.2f) alpha = 0.1f - 0.5f*o;
        else if (o >= 0.8f) alpha = 0.5f*o - 0.4f;
        else                alpha = 0.f;
        out[BATCH + gw] = alpha;
    }
}

extern "C" void kernel_launch(void* const* d_in, const int* in_sizes, int n_in,
                              void* d_out, int out_size)
{
    const float* x  = (const float*)d_in[0];
    const float* W0 = (const float*)d_in[1];
    const float* b0 = (const float*)d_in[2];
    const float* W1 = (const float*)d_in[3];
    const float* b1 = (const float*)d_in[4];
    const float* W2 = (const float*)d_in[5];
    const float* b2 = (const float*)d_in[6];
    float* out = (float*)d_out;

    __half *xh,*xl,*w0,*w1,*h0h,*h0l,*h1h,*h1l;
    cudaGetSymbolAddress((void**)&xh,  g_xh);  cudaGetSymbolAddress((void**)&xl,  g_xl);
    cudaGetSymbolAddress((void**)&w0,  g_w0);  cudaGetSymbolAddress((void**)&w1,  g_w1);
    cudaGetSymbolAddress((void**)&h0h, g_h0h); cudaGetSymbolAddress((void**)&h0l, g_h0l);
    cudaGetSymbolAddress((void**)&h1h, g_h1h); cudaGetSymbolAddress((void**)&h1l, g_h1l);

    cudaFuncSetAttribute(gemm_split, cudaFuncAttributeMaxDynamicSharedMemorySize, SMEM_SZ);

    cvt_x_k<<<(BATCH*NIN/4)/256, 256>>>(x, xh, xl);
    tr_cvt_k<<<dim3(NHID/32, NIN/32),  dim3(32,8)>>>(W0, w0, NIN,  NHID);
    tr_cvt_k<<<dim3(NHID/32, NHID/32), dim3(32,8)>>>(W1, w1, NHID, NHID);

    gemm_split<<<dim3(NHID/BN, BATCH/BM), 256, SMEM_SZ>>>(
        xh, xl, w0, b0, h0h, h0l, BATCH, NHID, NIN);
    gemm_split<<<dim3(NHID/BN, BATCH/BM), 256, SMEM_SZ>>>(
        h0h, h0l, w1, b1, h1h, h1l, BATCH, NHID, NHID);

    final_k<<<BATCH/8, 256>>>(h1h, h1l, W2, b2, out);
}

// round 14
// speedup vs baseline: 1.6162x; 1.0587x over previous
#include <cuda_runtime.h>
#include <cuda_fp16.h>
#include <stdint.h>

#define BATCH 32768
#define NIN   1024
#define NHID  2048

// ---- scratch (static __device__, no allocation) ----
__device__ __align__(256) __half g_xh [(size_t)BATCH*NIN];
__device__ __align__(256) __half g_xl [(size_t)BATCH*NIN];
__device__ __align__(256) __half g_w0 [(size_t)NHID*NIN];    // [n][k] fp16
__device__ __align__(256) __half g_w1 [(size_t)NHID*NHID];
__device__ __align__(256) __half g_h0h[(size_t)BATCH*NHID];
__device__ __align__(256) __half g_h0l[(size_t)BATCH*NHID];
__device__ __align__(256) __half g_h1h[(size_t)BATCH*NHID];
__device__ __align__(256) __half g_h1l[(size_t)BATCH*NHID];

// ---- helpers ----
__device__ __forceinline__ uint32_t s2u(const void* p){
    return (uint32_t)__cvta_generic_to_shared(p);
}
__device__ __forceinline__ void cp16(uint32_t d, const void* s){
    asm volatile("cp.async.cg.shared.global [%0], [%1], 16;\n" :: "r"(d), "l"(s));
}
__device__ __forceinline__ void ldm4(uint32_t&r0,uint32_t&r1,uint32_t&r2,uint32_t&r3,uint32_t a){
    asm volatile("ldmatrix.sync.aligned.m8n8.x4.shared.b16 {%0,%1,%2,%3},[%4];\n"
        : "=r"(r0),"=r"(r1),"=r"(r2),"=r"(r3) : "r"(a));
}
__device__ __forceinline__ void mma16816h(float* c, const uint32_t* a, const uint32_t* b){
    asm volatile("mma.sync.aligned.m16n8k16.row.col.f32.f16.f16.f32 "
        "{%0,%1,%2,%3},{%4,%5,%6,%7},{%8,%9},{%0,%1,%2,%3};\n"
        : "+f"(c[0]),"+f"(c[1]),"+f"(c[2]),"+f"(c[3])
        : "r"(a[0]),"r"(a[1]),"r"(a[2]),"r"(a[3]),"r"(b[0]),"r"(b[1]));
}
__device__ __forceinline__ float eluf(float x){ return x > 0.f ? x : (__expf(x) - 1.f); }
__device__ __forceinline__ void split_f16(float v, __half& h, __half& l){
    h = __float2half(v);
    l = __float2half(v - __half2float(h));
}

// ---- tile geometry: BM=128 x BN=128, 8 warps (4x2) of 32x64, 2 CTAs/SM ----
#define BM 128
#define BN 128
#define BK 32
#define ROWB 80                   // 64B data + 16B pad -> conflict-free ldmatrix
#define A_PLANE (128*80)          // 10240
#define B_PLANE (128*80)          // 10240
#define STAGEB  (2*A_PLANE + B_PLANE)   // 30720: Ah, Al, B
#define NSTAGE 3
#define SMEM_SZ (NSTAGE*STAGEB)   // 92160/CTA -> 184320 for 2 CTAs
#define P_AH 0u
#define P_AL 10240u
#define P_B  20480u

// fragment set for one ks half-chunk (single buffer; 96 regs live)
struct Frag {
    uint32_t ah[2][4], al[2][4];
    uint32_t b[8][2];
};

// C = elu((Ah+Al) @ W^T + bias); A split fp16 hi/lo, W single fp16; fp32 accum.
// 256 threads, 8 warps (4x2, 32x64 warp tiles), 3-stage cp.async pipeline,
// term-major mma (acc reuse dist = 16), 2 independent CTAs/SM.
__global__ void __launch_bounds__(256,2)
gemm_split(const __half* __restrict__ Ah, const __half* __restrict__ Al,
           const __half* __restrict__ Bw,
           const float* __restrict__ bias,
           __half* __restrict__ Ch, __half* __restrict__ Cl,
           int M, int N, int K)
{
    extern __shared__ __align__(16) unsigned char sm[];
    const uint32_t sb = s2u(sm);
    const int tid = threadIdx.x;
    const int m0 = blockIdx.y * BM;
    const int n0 = blockIdx.x * BN;
    const int KT = K / BK;

    // A: 128 rows x 4 chunks = 512 slots (2/thread) per plane; B same
    const int ac = tid & 3;
    auto load = [&](int kt, int st){
        const int kk = kt * BK;
        const uint32_t s0 = sb + (uint32_t)st*STAGEB;
        #pragma unroll
        for (int i = 0; i < 2; i++){
            const int row = (tid >> 2) + i*64;     // 0..127
            const uint32_t dso = (uint32_t)(row*ROWB + ac*16);
            const size_t ao = (size_t)(m0+row)*K + kk + ac*8;
            const size_t bo = (size_t)(n0+row)*K + kk + ac*8;
            cp16(s0 + P_AH + dso, Ah + ao);
            cp16(s0 + P_AL + dso, Al + ao);
            cp16(s0 + P_B  + dso, Bw + bo);
        }
        asm volatile("cp.async.commit_group;\n" ::: "memory");
    };

    const int warp = tid >> 5, lane = tid & 31;
    const int wr = warp >> 1, wc = warp & 1;   // 4x2 grid of 32x64 tiles

    const int a_row  = wr*32 + (lane & 15);
    const int a_colb = (lane >> 4) * 16;
    const int b_row  = wc*64 + (lane >> 4)*8 + (lane & 7);
    const int b_colb = ((lane >> 3) & 1) * 16;

    auto ldfrags = [&](int st, int ks, Frag& f){
        const uint32_t s0 = sb + (uint32_t)st*STAGEB;
        #pragma unroll
        for (int i = 0; i < 2; i++){
            const uint32_t ro = (uint32_t)(a_row + i*16)*ROWB + a_colb + ks*32;
            ldm4(f.ah[i][0],f.ah[i][1],f.ah[i][2],f.ah[i][3], s0 + P_AH + ro);
            ldm4(f.al[i][0],f.al[i][1],f.al[i][2],f.al[i][3], s0 + P_AL + ro);
        }
        #pragma unroll
        for (int p = 0; p < 4; p++){
            const uint32_t ro = (uint32_t)(b_row + p*16)*ROWB + b_colb + ks*32;
            uint32_t r0,r1,r2,r3;
            ldm4(r0,r1,r2,r3, s0 + P_B + ro);
            f.b[p*2][0]=r0; f.b[p*2][1]=r1; f.b[p*2+1][0]=r2; f.b[p*2+1][1]=r3;
        }
    };

    float acc[2][8][4];
    #pragma unroll
    for (int i=0;i<2;i++)
        #pragma unroll
        for (int j=0;j<8;j++)
            #pragma unroll
            for (int k=0;k<4;k++) acc[i][j][k] = 0.f;

    // term-major: same-acc mmas are 16 apart -> HMMA RAW latency hidden
    auto mma2 = [&](const Frag& f){
        #pragma unroll
        for (int t = 0; t < 2; t++){
            const uint32_t (*fa)[4] = (t == 1) ? f.al : f.ah;
            #pragma unroll
            for (int i = 0; i < 2; i++)
                #pragma unroll
                for (int j = 0; j < 8; j++)
                    mma16816h(acc[i][j], fa[i], f.b[j]);
        }
    };

    load(0, 0);
    load(1, 1);

    Frag F;
    for (int kt = 0; kt < KT; kt++){
        if (kt < KT-1) asm volatile("cp.async.wait_group 1;\n" ::: "memory");
        else           asm volatile("cp.async.wait_group 0;\n" ::: "memory");
        __syncthreads();
        if (kt + 2 < KT) load(kt + 2, (kt + 2) % NSTAGE);
        const int st = kt % NSTAGE;

        ldfrags(st, 0, F);
        mma2(F);
        ldfrags(st, 1, F);
        mma2(F);
    }

    // epilogue: bias + elu -> hi/lo fp16 planes
    const int gid = lane >> 2, tig = lane & 3;
    #pragma unroll
    for (int i = 0; i < 2; i++){
        const int mrow = m0 + wr*32 + i*16 + gid;
        #pragma unroll
        for (int j = 0; j < 8; j++){
            const int n = n0 + wc*64 + j*8 + tig*2;
            const float2 bv = *(const float2*)&bias[n];
            float v[4] = {acc[i][j][0] + bv.x, acc[i][j][1] + bv.y,
                          acc[i][j][2] + bv.x, acc[i][j][3] + bv.y};
            v[0]=eluf(v[0]); v[1]=eluf(v[1]); v[2]=eluf(v[2]); v[3]=eluf(v[3]);
            __half h[4], l[4];
            #pragma unroll
            for (int q = 0; q < 4; q++) split_f16(v[q], h[q], l[q]);
            const size_t o0 = (size_t)mrow*N + n, o1 = (size_t)(mrow+8)*N + n;
            *(__half2*)&Ch[o0] = *(__half2*)&h[0];
            *(__half2*)&Cl[o0] = *(__half2*)&l[0];
            *(__half2*)&Ch[o1] = *(__half2*)&h[2];
            *(__half2*)&Cl[o1] = *(__half2*)&l[2];
        }
    }
}

// fp32 x -> hi/lo fp16 planes
__global__ void cvt_x_k(const float* __restrict__ x,
                        __half* __restrict__ xh, __half* __restrict__ xl){
    size_t i = (size_t)blockIdx.x * blockDim.x + threadIdx.x;
    float4 v = ((const float4*)x)[i];
    __half h[4], l[4];
    split_f16(v.x, h[0], l[0]); split_f16(v.y, h[1], l[1]);
    split_f16(v.z, h[2], l[2]); split_f16(v.w, h[3], l[3]);
    ((uint2*)xh)[i] = *(uint2*)h;
    ((uint2*)xl)[i] = *(uint2*)l;
}

// w[k][n] fp32 -> wt [n][k] single fp16
__global__ void tr_cvt_k(const float* __restrict__ w,
                         __half* __restrict__ wt, int K, int N){
    __shared__ float t[32][33];
    const int n0 = blockIdx.x*32, k0 = blockIdx.y*32;
    #pragma unroll
    for (int r = threadIdx.y; r < 32; r += 8)
        t[r][threadIdx.x] = w[(size_t)(k0+r)*N + n0 + threadIdx.x];
    __syncthreads();
    #pragma unroll
    for (int r = threadIdx.y; r < 32; r += 8)
        wt[(size_t)(n0+r)*K + k0 + threadIdx.x] = __float2half(t[threadIdx.x][r]);
}

// layer 3: warp-per-row matvec (hi+lo reconstruct) + sigmoid + alpha
__global__ void final_k(const __half* __restrict__ hh, const __half* __restrict__ hl,
                        const float* __restrict__ w2, const float* __restrict__ b2,
                        float* __restrict__ out){
    const int gw   = (blockIdx.x*blockDim.x + threadIdx.x) >> 5;
    const int lane = threadIdx.x & 31;
    const __half* rh = hh + (size_t)gw * NHID;
    const __half* rl = hl + (size_t)gw * NHID;
    float s = 0.f;
    #pragma unroll
    for (int it = 0; it < NHID/256; it++){
        const int k = it*256 + lane*8;
        uint4 hv = *(const uint4*)(rh + k);
        uint4 lv = *(const uint4*)(rl + k);
        const __half2* hp = (const __half2*)&hv;
        const __half2* lp = (const __half2*)&lv;
        float4 wa = *(const float4*)(w2 + k);
        float4 wb = *(const float4*)(w2 + k + 4);
        float2 f0 = __half22float2(hp[0]), g0 = __half22float2(lp[0]);
        float2 f1 = __half22float2(hp[1]), g1 = __half22float2(lp[1]);
        float2 f2 = __half22float2(hp[2]), g2 = __half22float2(lp[2]);
        float2 f3 = __half22float2(hp[3]), g3 = __half22float2(lp[3]);
        s += (f0.x+g0.x)*wa.x + (f0.y+g0.y)*wa.y + (f1.x+g1.x)*wa.z + (f1.y+g1.y)*wa.w
           + (f2.x+g2.x)*wb.x + (f2.y+g2.y)*wb.y + (f3.x+g3.x)*wb.z + (f3.y+g3.y)*wb.w;
    }
    #pragma unroll
    for (int o = 16; o; o >>= 1) s += __shfl_xor_sync(0xffffffffu, s, o);
    if (lane == 0){
        const float z = s + b2[0];
        const float o = 1.f / (1.f + __expf(-z));
        out[gw] = o;
        float alpha;
        if      (o <= 0.2f) alpha = 0.1f - 0.5f*o;
        else if (o >= 0.8f) alpha = 0.5f*o - 0.4f;
        else                alpha = 0.f;
        out[BATCH + gw] = alpha;
    }
}

extern "C" void kernel_launch(void* const* d_in, const int* in_sizes, int n_in,
                              void* d_out, int out_size)
{
    const float* x  = (const float*)d_in[0];
    const float* W0 = (const float*)d_in[1];
    const float* b0 = (const float*)d_in[2];
    const float* W1 = (const float*)d_in[3];
    const float* b1 = (const float*)d_in[4];
    const float* W2 = (const float*)d_in[5];
    const float* b2 = (const float*)d_in[6];
    float* out = (float*)d_out;

    __half *xh,*xl,*w0,*w1,*h0h,*h0l,*h1h,*h1l;
    cudaGetSymbolAddress((void**)&xh,  g_xh);  cudaGetSymbolAddress((void**)&xl,  g_xl);
    cudaGetSymbolAddress((void**)&w0,  g_w0);  cudaGetSymbolAddress((void**)&w1,  g_w1);
    cudaGetSymbolAddress((void**)&h0h, g_h0h); cudaGetSymbolAddress((void**)&h0l, g_h0l);
    cudaGetSymbolAddress((void**)&h1h, g_h1h); cudaGetSymbolAddress((void**)&h1l, g_h1l);

    cudaFuncSetAttribute(gemm_split, cudaFuncAttributeMaxDynamicSharedMemorySize, SMEM_SZ);

    cvt_x_k<<<(BATCH*NIN/4)/256, 256>>>(x, xh, xl);
    tr_cvt_k<<<dim3(NHID/32, NIN/32),  dim3(32,8)>>>(W0, w0, NIN,  NHID);
    tr_cvt_k<<<dim3(NHID/32, NHID/32), dim3(32,8)>>>(W1, w1, NHID, NHID);

    gemm_split<<<dim3(NHID/BN, BATCH/BM), 256, SMEM_SZ>>>(
        xh, xl, w0, b0, h0h, h0l, BATCH, NHID, NIN);
    gemm_split<<<dim3(NHID/BN, BATCH/BM), 256, SMEM_SZ>>>(
        h0h, h0l, w1, b1, h1h, h1l, BATCH, NHID, NHID);

    final_k<<<BATCH/8, 256>>>(h1h, h1l, W2, b2, out);
}

// round 15
// speedup vs baseline: 1.6165x; 1.0002x over previous
#include <cuda_runtime.h>
#include <cuda_fp16.h>
#include <stdint.h>

#define BATCH 32768
#define NIN   1024
#define NHID  2048

// ---- scratch (static __device__, no allocation) ----
__device__ __align__(256) __half g_xh [(size_t)BATCH*NIN];
__device__ __align__(256) __half g_xl [(size_t)BATCH*NIN];
__device__ __align__(256) __half g_w0 [(size_t)NHID*NIN];    // [n][k] fp16
__device__ __align__(256) __half g_w1 [(size_t)NHID*NHID];
__device__ __align__(256) __half g_h0h[(size_t)BATCH*NHID];
__device__ __align__(256) __half g_h0l[(size_t)BATCH*NHID];
__device__ __align__(256) __half g_h1h[(size_t)BATCH*NHID];
__device__ __align__(256) __half g_h1l[(size_t)BATCH*NHID];

// ---- helpers ----
__device__ __forceinline__ uint32_t s2u(const void* p){
    return (uint32_t)__cvta_generic_to_shared(p);
}
__device__ __forceinline__ void cp16(uint32_t d, const void* s){
    asm volatile("cp.async.cg.shared.global [%0], [%1], 16;\n" :: "r"(d), "l"(s));
}
__device__ __forceinline__ void ldm4(uint32_t&r0,uint32_t&r1,uint32_t&r2,uint32_t&r3,uint32_t a){
    asm volatile("ldmatrix.sync.aligned.m8n8.x4.shared.b16 {%0,%1,%2,%3},[%4];\n"
        : "=r"(r0),"=r"(r1),"=r"(r2),"=r"(r3) : "r"(a));
}
__device__ __forceinline__ void mma16816h(float* c, const uint32_t* a, const uint32_t* b){
    asm volatile("mma.sync.aligned.m16n8k16.row.col.f32.f16.f16.f32 "
        "{%0,%1,%2,%3},{%4,%5,%6,%7},{%8,%9},{%0,%1,%2,%3};\n"
        : "+f"(c[0]),"+f"(c[1]),"+f"(c[2]),"+f"(c[3])
        : "r"(a[0]),"r"(a[1]),"r"(a[2]),"r"(a[3]),"r"(b[0]),"r"(b[1]));
}
__device__ __forceinline__ float eluf(float x){ return x > 0.f ? x : (__expf(x) - 1.f); }
__device__ __forceinline__ void split_f16(float v, __half& h, __half& l){
    h = __float2half(v);
    l = __float2half(v - __half2float(h));
}

// ---- tile geometry: BM=128 x BN=128, 8 warps (4x2) of 32x64, 2 CTAs/SM ----
#define BM 128
#define BN 128
#define BK 32
#define ROWB 80                   // 64B data + 16B pad -> conflict-free ldmatrix
#define A_PLANE (128*80)          // 10240
#define B_PLANE (128*80)          // 10240
#define STAGEB  (2*A_PLANE + B_PLANE)   // 30720: Ah, Al, B
#define NSTAGE 3
#define SMEM_SZ (NSTAGE*STAGEB)   // 92160/CTA -> 184320 for 2 CTAs
#define P_AH 0u
#define P_AL 10240u
#define P_B  20480u

// C = elu((Ah+Al) @ W^T + bias); A split fp16 hi/lo, W single fp16; fp32 accum.
// 256 threads, 8 warps (4x2, 32x64 warp tiles), 3-stage cp.async pipeline,
// B-fragment j-half double buffering: every LDSM burst overlaps an mma burst.
__global__ void __launch_bounds__(256,2)
gemm_split(const __half* __restrict__ Ah, const __half* __restrict__ Al,
           const __half* __restrict__ Bw,
           const float* __restrict__ bias,
           __half* __restrict__ Ch, __half* __restrict__ Cl,
           int M, int N, int K)
{
    extern __shared__ __align__(16) unsigned char sm[];
    const uint32_t sb = s2u(sm);
    const int tid = threadIdx.x;
    const int m0 = blockIdx.y * BM;
    const int n0 = blockIdx.x * BN;
    const int KT = K / BK;

    const int ac = tid & 3;
    auto load = [&](int kt, int st){
        const int kk = kt * BK;
        const uint32_t s0 = sb + (uint32_t)st*STAGEB;
        #pragma unroll
        for (int i = 0; i < 2; i++){
            const int row = (tid >> 2) + i*64;     // 0..127
            const uint32_t dso = (uint32_t)(row*ROWB + ac*16);
            const size_t ao = (size_t)(m0+row)*K + kk + ac*8;
            const size_t bo = (size_t)(n0+row)*K + kk + ac*8;
            cp16(s0 + P_AH + dso, Ah + ao);
            cp16(s0 + P_AL + dso, Al + ao);
            cp16(s0 + P_B  + dso, Bw + bo);
        }
        asm volatile("cp.async.commit_group;\n" ::: "memory");
    };

    const int warp = tid >> 5, lane = tid & 31;
    const int wr = warp >> 1, wc = warp & 1;   // 4x2 grid of 32x64 tiles

    const int a_row  = wr*32 + (lane & 15);
    const int a_colb = (lane >> 4) * 16;
    const int b_row  = wc*64 + (lane >> 4)*8 + (lane & 7);
    const int b_colb = ((lane >> 3) & 1) * 16;

    uint32_t ah[2][4], al[2][4];     // A frags for current ks (32 regs)
    uint32_t b0[4][2], b1[4][2];     // B j-half frags (8+8 regs)

    auto ldA = [&](uint32_t s0, int ks){
        #pragma unroll
        for (int i = 0; i < 2; i++){
            const uint32_t ro = (uint32_t)(a_row + i*16)*ROWB + a_colb + ks*32;
            ldm4(ah[i][0],ah[i][1],ah[i][2],ah[i][3], s0 + P_AH + ro);
            ldm4(al[i][0],al[i][1],al[i][2],al[i][3], s0 + P_AL + ro);
        }
    };
    auto ldB = [&](uint32_t s0, int ks, int half, uint32_t bb[4][2]){
        #pragma unroll
        for (int p = 0; p < 2; p++){
            const uint32_t ro = (uint32_t)(b_row + (half*2+p)*16)*ROWB + b_colb + ks*32;
            uint32_t r0,r1,r2,r3;
            ldm4(r0,r1,r2,r3, s0 + P_B + ro);
            bb[p*2][0]=r0; bb[p*2][1]=r1; bb[p*2+1][0]=r2; bb[p*2+1][1]=r3;
        }
    };

    float acc[2][8][4];
    #pragma unroll
    for (int i=0;i<2;i++)
        #pragma unroll
        for (int j=0;j<8;j++)
            #pragma unroll
            for (int k=0;k<4;k++) acc[i][j][k] = 0.f;

    // 16 mmas over one B j-half; term-major keeps same-acc distance = 8
    auto mmaHalf = [&](const uint32_t bb[4][2], int jbase){
        #pragma unroll
        for (int t = 0; t < 2; t++){
            const uint32_t (*fa)[4] = (t == 1) ? al : ah;
            #pragma unroll
            for (int i = 0; i < 2; i++)
                #pragma unroll
                for (int j = 0; j < 4; j++)
                    mma16816h(acc[i][jbase+j], fa[i], bb[j]);
        }
    };

    load(0, 0);
    load(1, 1);

    for (int kt = 0; kt < KT; kt++){
        if (kt < KT-1) asm volatile("cp.async.wait_group 1;\n" ::: "memory");
        else           asm volatile("cp.async.wait_group 0;\n" ::: "memory");
        __syncthreads();
        if (kt + 2 < KT) load(kt + 2, (kt + 2) % NSTAGE);
        const uint32_t s0 = sb + (uint32_t)((kt % NSTAGE)*STAGEB);

        // ks = 0
        ldA(s0, 0);
        ldB(s0, 0, 0, b0);
        ldB(s0, 0, 1, b1);
        mmaHalf(b0, 0);          // b1 LDSM lands under this burst
        ldB(s0, 1, 0, b0);       // prefetch ks=1 half-0 under mma(b1)
        mmaHalf(b1, 4);
        // ks = 1
        ldA(s0, 1);              // A reload overlaps tail of mma(b1)
        ldB(s0, 1, 1, b1);
        mmaHalf(b0, 0);
        mmaHalf(b1, 4);
    }

    // epilogue: bias + elu -> hi/lo fp16 planes
    const int gid = lane >> 2, tig = lane & 3;
    #pragma unroll
    for (int i = 0; i < 2; i++){
        const int mrow = m0 + wr*32 + i*16 + gid;
        #pragma unroll
        for (int j = 0; j < 8; j++){
            const int n = n0 + wc*64 + j*8 + tig*2;
            const float2 bv = *(const float2*)&bias[n];
            float v[4] = {acc[i][j][0] + bv.x, acc[i][j][1] + bv.y,
                          acc[i][j][2] + bv.x, acc[i][j][3] + bv.y};
            v[0]=eluf(v[0]); v[1]=eluf(v[1]); v[2]=eluf(v[2]); v[3]=eluf(v[3]);
            __half h[4], l[4];
            #pragma unroll
            for (int q = 0; q < 4; q++) split_f16(v[q], h[q], l[q]);
            const size_t o0 = (size_t)mrow*N + n, o1 = (size_t)(mrow+8)*N + n;
            *(__half2*)&Ch[o0] = *(__half2*)&h[0];
            *(__half2*)&Cl[o0] = *(__half2*)&l[0];
            *(__half2*)&Ch[o1] = *(__half2*)&h[2];
            *(__half2*)&Cl[o1] = *(__half2*)&l[2];
        }
    }
}

// fp32 x -> hi/lo fp16 planes
__global__ void cvt_x_k(const float* __restrict__ x,
                        __half* __restrict__ xh, __half* __restrict__ xl){
    size_t i = (size_t)blockIdx.x * blockDim.x + threadIdx.x;
    float4 v = ((const float4*)x)[i];
    __half h[4], l[4];
    split_f16(v.x, h[0], l[0]); split_f16(v.y, h[1], l[1]);
    split_f16(v.z, h[2], l[2]); split_f16(v.w, h[3], l[3]);
    ((uint2*)xh)[i] = *(uint2*)h;
    ((uint2*)xl)[i] = *(uint2*)l;
}

// w[k][n] fp32 -> wt [n][k] single fp16
__global__ void tr_cvt_k(const float* __restrict__ w,
                         __half* __restrict__ wt, int K, int N){
    __shared__ float t[32][33];
    const int n0 = blockIdx.x*32, k0 = blockIdx.y*32;
    #pragma unroll
    for (int r = threadIdx.y; r < 32; r += 8)
        t[r][threadIdx.x] = w[(size_t)(k0+r)*N + n0 + threadIdx.x];
    __syncthreads();
    #pragma unroll
    for (int r = threadIdx.y; r < 32; r += 8)
        wt[(size_t)(n0+r)*K + k0 + threadIdx.x] = __float2half(t[threadIdx.x][r]);
}

// layer 3: warp-per-row matvec (hi+lo reconstruct) + sigmoid + alpha
__global__ void final_k(const __half* __restrict__ hh, const __half* __restrict__ hl,
                        const float* __restrict__ w2, const float* __restrict__ b2,
                        float* __restrict__ out){
    const int gw   = (blockIdx.x*blockDim.x + threadIdx.x) >> 5;
    const int lane = threadIdx.x & 31;
    const __half* rh = hh + (size_t)gw * NHID;
    const __half* rl = hl + (size_t)gw * NHID;
    float s = 0.f;
    #pragma unroll
    for (int it = 0; it < NHID/256; it++){
        const int k = it*256 + lane*8;
        uint4 hv = *(const uint4*)(rh + k);
        uint4 lv = *(const uint4*)(rl + k);
        const __half2* hp = (const __half2*)&hv;
        const __half2* lp = (const __half2*)&lv;
        float4 wa = *(const float4*)(w2 + k);
        float4 wb = *(const float4*)(w2 + k + 4);
        float2 f0 = __half22float2(hp[0]), g0 = __half22float2(lp[0]);
        float2 f1 = __half22float2(hp[1]), g1 = __half22float2(lp[1]);
        float2 f2 = __half22float2(hp[2]), g2 = __half22float2(lp[2]);
        float2 f3 = __half22float2(hp[3]), g3 = __half22float2(lp[3]);
        s += (f0.x+g0.x)*wa.x + (f0.y+g0.y)*wa.y + (f1.x+g1.x)*wa.z + (f1.y+g1.y)*wa.w
           + (f2.x+g2.x)*wb.x + (f2.y+g2.y)*wb.y + (f3.x+g3.x)*wb.z + (f3.y+g3.y)*wb.w;
    }
    #pragma unroll
    for (int o = 16; o; o >>= 1) s += __shfl_xor_sync(0xffffffffu, s, o);
    if (lane == 0){
        const float z = s + b2[0];
        const float o = 1.f / (1.f + __expf(-z));
        out[gw] = o;
        float alpha;
        if      (o <= 0.2f) alpha = 0.1f - 0.5f*o;
        else if (o >= 0.8f) alpha = 0.5f*o - 0.4f;
        else                alpha = 0.f;
        out[BATCH + gw] = alpha;
    }
}

extern "C" void kernel_launch(void* const* d_in, const int* in_sizes, int n_in,
                              void* d_out, int out_size)
{
    const float* x  = (const float*)d_in[0];
    const float* W0 = (const float*)d_in[1];
    const float* b0 = (const float*)d_in[2];
    const float* W1 = (const float*)d_in[3];
    const float* b1 = (const float*)d_in[4];
    const float* W2 = (const float*)d_in[5];
    const float* b2 = (const float*)d_in[6];
    float* out = (float*)d_out;

    __half *xh,*xl,*w0,*w1,*h0h,*h0l,*h1h,*h1l;
    cudaGetSymbolAddress((void**)&xh,  g_xh);  cudaGetSymbolAddress((void**)&xl,  g_xl);
    cudaGetSymbolAddress((void**)&w0,  g_w0);  cudaGetSymbolAddress((void**)&w1,  g_w1);
    cudaGetSymbolAddress((void**)&h0h, g_h0h); cudaGetSymbolAddress((void**)&h0l, g_h0l);
    cudaGetSymbolAddress((void**)&h1h, g_h1h); cudaGetSymbolAddress((void**)&h1l, g_h1l);

    cudaFuncSetAttribute(gemm_split, cudaFuncAttributeMaxDynamicSharedMemorySize, SMEM_SZ);

    cvt_x_k<<<(BATCH*NIN/4)/256, 256>>>(x, xh, xl);
    tr_cvt_k<<<dim3(NHID/32, NIN/32),  dim3(32,8)>>>(W0, w0, NIN,  NHID);
    tr_cvt_k<<<dim3(NHID/32, NHID/32), dim3(32,8)>>>(W1, w1, NHID, NHID);

    gemm_split<<<dim3(NHID/BN, BATCH/BM), 256, SMEM_SZ>>>(
        xh, xl, w0, b0, h0h, h0l, BATCH, NHID, NIN);
    gemm_split<<<dim3(NHID/BN, BATCH/BM), 256, SMEM_SZ>>>(
        h0h, h0l, w1, b1, h1h, h1l, BATCH, NHID, NHID);

    final_k<<<BATCH/8, 256>>>(h1h, h1l, W2, b2, out);
}

// round 16
// speedup vs baseline: 2.1999x; 1.3609x over previous
#include <cuda_runtime.h>
#include <cuda_fp16.h>
#include <stdint.h>

#define BATCH 32768
#define NIN   1024
#define NHID  2048

// ---- scratch (static __device__, no allocation) ----
__device__ __align__(256) __half g_xh [(size_t)BATCH*NIN];
__device__ __align__(256) __half g_xl [(size_t)BATCH*NIN];
__device__ __align__(256) __half g_w0 [(size_t)NHID*NIN];    // [n][k] fp16
__device__ __align__(256) __half g_w1 [(size_t)NHID*NHID];
__device__ __align__(256) __half g_h0 [(size_t)BATCH*NHID];  // single fp16 plane
__device__ __align__(256) __half g_h1h[(size_t)BATCH*NHID];
__device__ __align__(256) __half g_h1l[(size_t)BATCH*NHID];

// ---- helpers ----
__device__ __forceinline__ uint32_t s2u(const void* p){
    return (uint32_t)__cvta_generic_to_shared(p);
}
__device__ __forceinline__ void cp16(uint32_t d, const void* s){
    asm volatile("cp.async.cg.shared.global [%0], [%1], 16;\n" :: "r"(d), "l"(s));
}
__device__ __forceinline__ void ldm4(uint32_t&r0,uint32_t&r1,uint32_t&r2,uint32_t&r3,uint32_t a){
    asm volatile("ldmatrix.sync.aligned.m8n8.x4.shared.b16 {%0,%1,%2,%3},[%4];\n"
        : "=r"(r0),"=r"(r1),"=r"(r2),"=r"(r3) : "r"(a));
}
__device__ __forceinline__ void mma16816h(float* c, const uint32_t* a, const uint32_t* b){
    asm volatile("mma.sync.aligned.m16n8k16.row.col.f32.f16.f16.f32 "
        "{%0,%1,%2,%3},{%4,%5,%6,%7},{%8,%9},{%0,%1,%2,%3};\n"
        : "+f"(c[0]),"+f"(c[1]),"+f"(c[2]),"+f"(c[3])
        : "r"(a[0]),"r"(a[1]),"r"(a[2]),"r"(a[3]),"r"(b[0]),"r"(b[1]));
}
__device__ __forceinline__ float eluf(float x){ return x > 0.f ? x : (__expf(x) - 1.f); }
__device__ __forceinline__ void split_f16(float v, __half& h, __half& l){
    h = __float2half(v);
    l = __float2half(v - __half2float(h));
}

// ---- tile geometry: BM=128 x BN=128, 8 warps (4x2) of 32x64, 2 CTAs/SM ----
#define BM 128
#define BN 128
#define BK 32
#define ROWB 80                   // 64B data + 16B pad -> conflict-free ldmatrix
#define PLANE (128*80)            // 10240 B
#define NSTAGE 3

// C = elu(A @ W^T + bias); A is 1 or 2 fp16 planes; W single fp16; fp32 accum.
// 256 threads, 8 warps (4x2, 32x64 warp tiles), 3-stage cp.async pipeline,
// term-major mma, 2 independent CTAs/SM.
template<int TWOA, int STORELO>
__global__ void __launch_bounds__(256,2)
gemm_split(const __half* __restrict__ Ah, const __half* __restrict__ Al,
           const __half* __restrict__ Bw,
           const float* __restrict__ bias,
           __half* __restrict__ Ch, __half* __restrict__ Cl,
           int M, int N, int K)
{
    constexpr uint32_t NPLANES = TWOA ? 3 : 2;     // Ah[,Al],B
    constexpr uint32_t STAGEB  = NPLANES * PLANE;
    constexpr uint32_t P_AL    = PLANE;            // valid only if TWOA
    constexpr uint32_t P_B     = (TWOA ? 2 : 1) * PLANE;

    extern __shared__ __align__(16) unsigned char sm[];
    const uint32_t sb = s2u(sm);
    const int tid = threadIdx.x;
    const int m0 = blockIdx.y * BM;
    const int n0 = blockIdx.x * BN;
    const int KT = K / BK;

    const int ac = tid & 3;
    auto load = [&](int kt, int st){
        const int kk = kt * BK;
        const uint32_t s0 = sb + (uint32_t)st*STAGEB;
        #pragma unroll
        for (int i = 0; i < 2; i++){
            const int row = (tid >> 2) + i*64;     // 0..127
            const uint32_t dso = (uint32_t)(row*ROWB + ac*16);
            const size_t ao = (size_t)(m0+row)*K + kk + ac*8;
            const size_t bo = (size_t)(n0+row)*K + kk + ac*8;
            cp16(s0 + dso, Ah + ao);
            if (TWOA) cp16(s0 + P_AL + dso, Al + ao);
            cp16(s0 + P_B + dso, Bw + bo);
        }
        asm volatile("cp.async.commit_group;\n" ::: "memory");
    };

    const int warp = tid >> 5, lane = tid & 31;
    const int wr = warp >> 1, wc = warp & 1;   // 4x2 grid of 32x64 tiles

    const int a_row  = wr*32 + (lane & 15);
    const int a_colb = (lane >> 4) * 16;
    const int b_row  = wc*64 + (lane >> 4)*8 + (lane & 7);
    const int b_colb = ((lane >> 3) & 1) * 16;

    uint32_t ah[2][4], al[2][4];
    uint32_t bf[8][2];

    auto ldA = [&](uint32_t s0, int ks){
        #pragma unroll
        for (int i = 0; i < 2; i++){
            const uint32_t ro = (uint32_t)(a_row + i*16)*ROWB + a_colb + ks*32;
            ldm4(ah[i][0],ah[i][1],ah[i][2],ah[i][3], s0 + ro);
            if (TWOA) ldm4(al[i][0],al[i][1],al[i][2],al[i][3], s0 + P_AL + ro);
        }
    };
    auto ldB = [&](uint32_t s0, int ks){
        #pragma unroll
        for (int p = 0; p < 4; p++){
            const uint32_t ro = (uint32_t)(b_row + p*16)*ROWB + b_colb + ks*32;
            uint32_t r0,r1,r2,r3;
            ldm4(r0,r1,r2,r3, s0 + P_B + ro);
            bf[p*2][0]=r0; bf[p*2][1]=r1; bf[p*2+1][0]=r2; bf[p*2+1][1]=r3;
        }
    };

    float acc[2][8][4];
    #pragma unroll
    for (int i=0;i<2;i++)
        #pragma unroll
        for (int j=0;j<8;j++)
            #pragma unroll
            for (int k=0;k<4;k++) acc[i][j][k] = 0.f;

    // term-major: same-acc mmas 16 apart -> RAW fully hidden
    auto mmaAll = [&](){
        #pragma unroll
        for (int t = 0; t < (TWOA ? 2 : 1); t++){
            const uint32_t (*fa)[4] = (t == 1) ? al : ah;
            #pragma unroll
            for (int i = 0; i < 2; i++)
                #pragma unroll
                for (int j = 0; j < 8; j++)
                    mma16816h(acc[i][j], fa[i], bf[j]);
        }
    };

    load(0, 0);
    load(1, 1);

    for (int kt = 0; kt < KT; kt++){
        if (kt < KT-1) asm volatile("cp.async.wait_group 1;\n" ::: "memory");
        else           asm volatile("cp.async.wait_group 0;\n" ::: "memory");
        __syncthreads();
        if (kt + 2 < KT) load(kt + 2, (kt + 2) % NSTAGE);
        const uint32_t s0 = sb + (uint32_t)((kt % NSTAGE)*STAGEB);

        ldA(s0, 0); ldB(s0, 0);
        mmaAll();
        ldA(s0, 1); ldB(s0, 1);
        mmaAll();
    }

    // epilogue: bias + elu -> fp16 (hi only, or hi/lo)
    const int gid = lane >> 2, tig = lane & 3;
    #pragma unroll
    for (int i = 0; i < 2; i++){
        const int mrow = m0 + wr*32 + i*16 + gid;
        #pragma unroll
        for (int j = 0; j < 8; j++){
            const int n = n0 + wc*64 + j*8 + tig*2;
            const float2 bv = *(const float2*)&bias[n];
            float v[4] = {acc[i][j][0] + bv.x, acc[i][j][1] + bv.y,
                          acc[i][j][2] + bv.x, acc[i][j][3] + bv.y};
            v[0]=eluf(v[0]); v[1]=eluf(v[1]); v[2]=eluf(v[2]); v[3]=eluf(v[3]);
            __half h[4], l[4];
            #pragma unroll
            for (int q = 0; q < 4; q++) split_f16(v[q], h[q], l[q]);
            const size_t o0 = (size_t)mrow*N + n, o1 = (size_t)(mrow+8)*N + n;
            *(__half2*)&Ch[o0] = *(__half2*)&h[0];
            *(__half2*)&Ch[o1] = *(__half2*)&h[2];
            if (STORELO){
                *(__half2*)&Cl[o0] = *(__half2*)&l[0];
                *(__half2*)&Cl[o1] = *(__half2*)&l[2];
            }
        }
    }
}

// fp32 x -> hi/lo fp16 planes
__global__ void cvt_x_k(const float* __restrict__ x,
                        __half* __restrict__ xh, __half* __restrict__ xl){
    size_t i = (size_t)blockIdx.x * blockDim.x + threadIdx.x;
    float4 v = ((const float4*)x)[i];
    __half h[4], l[4];
    split_f16(v.x, h[0], l[0]); split_f16(v.y, h[1], l[1]);
    split_f16(v.z, h[2], l[2]); split_f16(v.w, h[3], l[3]);
    ((uint2*)xh)[i] = *(uint2*)h;
    ((uint2*)xl)[i] = *(uint2*)l;
}

// w[k][n] fp32 -> wt [n][k] single fp16
__global__ void tr_cvt_k(const float* __restrict__ w,
                         __half* __restrict__ wt, int K, int N){
    __shared__ float t[32][33];
    const int n0 = blockIdx.x*32, k0 = blockIdx.y*32;
    #pragma unroll
    for (int r = threadIdx.y; r < 32; r += 8)
        t[r][threadIdx.x] = w[(size_t)(k0+r)*N + n0 + threadIdx.x];
    __syncthreads();
    #pragma unroll
    for (int r = threadIdx.y; r < 32; r += 8)
        wt[(size_t)(n0+r)*K + k0 + threadIdx.x] = __float2half(t[threadIdx.x][r]);
}

// layer 3: warp-per-row matvec (hi+lo reconstruct) + sigmoid + alpha
__global__ void final_k(const __half* __restrict__ hh, const __half* __restrict__ hl,
                        const float* __restrict__ w2, const float* __restrict__ b2,
                        float* __restrict__ out){
    const int gw   = (blockIdx.x*blockDim.x + threadIdx.x) >> 5;
    const int lane = threadIdx.x & 31;
    const __half* rh = hh + (size_t)gw * NHID;
    const __half* rl = hl + (size_t)gw * NHID;
    float s = 0.f;
    #pragma unroll
    for (int it = 0; it < NHID/256; it++){
        const int k = it*256 + lane*8;
        uint4 hv = *(const uint4*)(rh + k);
        uint4 lv = *(const uint4*)(rl + k);
        const __half2* hp = (const __half2*)&hv;
        const __half2* lp = (const __half2*)&lv;
        float4 wa = *(const float4*)(w2 + k);
        float4 wb = *(const float4*)(w2 + k + 4);
        float2 f0 = __half22float2(hp[0]), g0 = __half22float2(lp[0]);
        float2 f1 = __half22float2(hp[1]), g1 = __half22float2(lp[1]);
        float2 f2 = __half22float2(hp[2]), g2 = __half22float2(lp[2]);
        float2 f3 = __half22float2(hp[3]), g3 = __half22float2(lp[3]);
        s += (f0.x+g0.x)*wa.x + (f0.y+g0.y)*wa.y + (f1.x+g1.x)*wa.z + (f1.y+g1.y)*wa.w
           + (f2.x+g2.x)*wb.x + (f2.y+g2.y)*wb.y + (f3.x+g3.x)*wb.z + (f3.y+g3.y)*wb.w;
    }
    #pragma unroll
    for (int o = 16; o; o >>= 1) s += __shfl_xor_sync(0xffffffffu, s, o);
    if (lane == 0){
        const float z = s + b2[0];
        const float o = 1.f / (1.f + __expf(-z));
        out[gw] = o;
        float alpha;
        if      (o <= 0.2f) alpha = 0.1f - 0.5f*o;
        else if (o >= 0.8f) alpha = 0.5f*o - 0.4f;
        else                alpha = 0.f;
        out[BATCH + gw] = alpha;
    }
}

extern "C" void kernel_launch(void* const* d_in, const int* in_sizes, int n_in,
                              void* d_out, int out_size)
{
    const float* x  = (const float*)d_in[0];
    const float* W0 = (const float*)d_in[1];
    const float* b0 = (const float*)d_in[2];
    const float* W1 = (const float*)d_in[3];
    const float* b1 = (const float*)d_in[4];
    const float* W2 = (const float*)d_in[5];
    const float* b2 = (const float*)d_in[6];
    float* out = (float*)d_out;

    __half *xh,*xl,*w0,*w1,*h0,*h1h,*h1l;
    cudaGetSymbolAddress((void**)&xh,  g_xh);  cudaGetSymbolAddress((void**)&xl,  g_xl);
    cudaGetSymbolAddress((void**)&w0,  g_w0);  cudaGetSymbolAddress((void**)&w1,  g_w1);
    cudaGetSymbolAddress((void**)&h0,  g_h0);
    cudaGetSymbolAddress((void**)&h1h, g_h1h); cudaGetSymbolAddress((void**)&h1l, g_h1l);

    const int SMEM_L0 = NSTAGE * 3 * PLANE;   // 92160 (2-plane A + B)
    const int SMEM_L1 = NSTAGE * 2 * PLANE;   // 61440 (1-plane A + B)
    cudaFuncSetAttribute(gemm_split<1,0>, cudaFuncAttributeMaxDynamicSharedMemorySize, SMEM_L0);
    cudaFuncSetAttribute(gemm_split<0,1>, cudaFuncAttributeMaxDynamicSharedMemorySize, SMEM_L1);

    cvt_x_k<<<(BATCH*NIN/4)/256, 256>>>(x, xh, xl);
    tr_cvt_k<<<dim3(NHID/32, NIN/32),  dim3(32,8)>>>(W0, w0, NIN,  NHID);
    tr_cvt_k<<<dim3(NHID/32, NHID/32), dim3(32,8)>>>(W1, w1, NHID, NHID);

    // L0: 2-term (xh+xl)@W0 -> h0 single fp16 plane
    gemm_split<1,0><<<dim3(NHID/BN, BATCH/BM), 256, SMEM_L0>>>(
        xh, xl, w0, b0, h0, nullptr, BATCH, NHID, NIN);
    // L1: 1-term h0@W1 -> h1 hi/lo
    gemm_split<0,1><<<dim3(NHID/BN, BATCH/BM), 256, SMEM_L1>>>(
        h0, nullptr, w1, b1, h1h, h1l, BATCH, NHID, NHID);

    final_k<<<BATCH/8, 256>>>(h1h, h1l, W2, b2, out);
}

// round 17
// speedup vs baseline: 2.2415x; 1.0189x over previous
#include <cuda_runtime.h>
#include <cuda_fp16.h>
#include <stdint.h>

#define BATCH 32768
#define NIN   1024
#define NHID  2048

// ---- scratch (static __device__, no allocation) ----
__device__ __align__(256) __half g_xh [(size_t)BATCH*NIN];
__device__ __align__(256) __half g_xl [(size_t)BATCH*NIN];
__device__ __align__(256) __half g_w0 [(size_t)NHID*NIN];    // [n][k] fp16
__device__ __align__(256) __half g_w1 [(size_t)NHID*NHID];
__device__ __align__(256) __half g_h0 [(size_t)BATCH*NHID];  // single fp16 plane
__device__ __align__(256) __half g_h1h[(size_t)BATCH*NHID];
__device__ __align__(256) __half g_h1l[(size_t)BATCH*NHID];

// ---- helpers ----
__device__ __forceinline__ uint32_t s2u(const void* p){
    return (uint32_t)__cvta_generic_to_shared(p);
}
__device__ __forceinline__ void cp16(uint32_t d, const void* s){
    asm volatile("cp.async.cg.shared.global [%0], [%1], 16;\n" :: "r"(d), "l"(s));
}
__device__ __forceinline__ void ldm4(uint32_t&r0,uint32_t&r1,uint32_t&r2,uint32_t&r3,uint32_t a){
    asm volatile("ldmatrix.sync.aligned.m8n8.x4.shared.b16 {%0,%1,%2,%3},[%4];\n"
        : "=r"(r0),"=r"(r1),"=r"(r2),"=r"(r3) : "r"(a));
}
__device__ __forceinline__ void mma16816h(float* c, const uint32_t* a, const uint32_t* b){
    asm volatile("mma.sync.aligned.m16n8k16.row.col.f32.f16.f16.f32 "
        "{%0,%1,%2,%3},{%4,%5,%6,%7},{%8,%9},{%0,%1,%2,%3};\n"
        : "+f"(c[0]),"+f"(c[1]),"+f"(c[2]),"+f"(c[3])
        : "r"(a[0]),"r"(a[1]),"r"(a[2]),"r"(a[3]),"r"(b[0]),"r"(b[1]));
}
__device__ __forceinline__ float eluf(float x){ return x > 0.f ? x : (__expf(x) - 1.f); }
__device__ __forceinline__ void split_f16(float v, __half& h, __half& l){
    h = __float2half(v);
    l = __float2half(v - __half2float(h));
}

// ---- tile geometry: BM=128 x BN=128, 8 warps (4x2) of 32x64, 2 CTAs/SM ----
#define BM 128
#define BN 128
#define BK 32
#define ROWB 80                   // 64B data + 16B pad -> conflict-free ldmatrix
#define PLANE (128*80)            // 10240 B
#define NSTAGE 3

// fragment set for one ks half-chunk (1-term path only)
struct Frag1 {
    uint32_t a[2][4];
    uint32_t b[8][2];
};

// C = elu(A @ W^T + bias); A is 1 or 2 fp16 planes; W single fp16; fp32 accum.
// 256 threads, 8 warps (4x2, 32x64 warp tiles), 3-stage cp.async pipeline,
// term-major mma, 2 independent CTAs/SM. 1-term path adds register
// fragment double-buffering (fits: 2x24 frag + 64 acc regs).
template<int TWOA, int STORELO>
__global__ void __launch_bounds__(256,2)
gemm_split(const __half* __restrict__ Ah, const __half* __restrict__ Al,
           const __half* __restrict__ Bw,
           const float* __restrict__ bias,
           __half* __restrict__ Ch, __half* __restrict__ Cl,
           int M, int N, int K)
{
    constexpr uint32_t STAGEB = (TWOA ? 3u : 2u) * PLANE;
    constexpr uint32_t P_AL   = PLANE;
    constexpr uint32_t P_B    = (TWOA ? 2u : 1u) * PLANE;

    extern __shared__ __align__(16) unsigned char sm[];
    const uint32_t sb = s2u(sm);
    const int tid = threadIdx.x;
    const int m0 = blockIdx.y * BM;
    const int n0 = blockIdx.x * BN;
    const int KT = K / BK;

    const int ac = tid & 3;
    auto load = [&](int kt, int st){
        const int kk = kt * BK;
        const uint32_t s0 = sb + (uint32_t)st*STAGEB;
        #pragma unroll
        for (int i = 0; i < 2; i++){
            const int row = (tid >> 2) + i*64;     // 0..127
            const uint32_t dso = (uint32_t)(row*ROWB + ac*16);
            const size_t ao = (size_t)(m0+row)*K + kk + ac*8;
            const size_t bo = (size_t)(n0+row)*K + kk + ac*8;
            cp16(s0 + dso, Ah + ao);
            if (TWOA) cp16(s0 + P_AL + dso, Al + ao);
            cp16(s0 + P_B + dso, Bw + bo);
        }
        asm volatile("cp.async.commit_group;\n" ::: "memory");
    };

    const int warp = tid >> 5, lane = tid & 31;
    const int wr = warp >> 1, wc = warp & 1;   // 4x2 grid of 32x64 tiles

    const int a_row  = wr*32 + (lane & 15);
    const int a_colb = (lane >> 4) * 16;
    const int b_row  = wc*64 + (lane >> 4)*8 + (lane & 7);
    const int b_colb = ((lane >> 3) & 1) * 16;

    float acc[2][8][4];
    #pragma unroll
    for (int i=0;i<2;i++)
        #pragma unroll
        for (int j=0;j<8;j++)
            #pragma unroll
            for (int k=0;k<4;k++) acc[i][j][k] = 0.f;

    if (TWOA){
        // ---- 2-term path (R16 structure, single frag buffer) ----
        uint32_t ah[2][4], al[2][4];
        uint32_t bf[8][2];
        auto ldA = [&](uint32_t s0, int ks){
            #pragma unroll
            for (int i = 0; i < 2; i++){
                const uint32_t ro = (uint32_t)(a_row + i*16)*ROWB + a_colb + ks*32;
                ldm4(ah[i][0],ah[i][1],ah[i][2],ah[i][3], s0 + ro);
                ldm4(al[i][0],al[i][1],al[i][2],al[i][3], s0 + P_AL + ro);
            }
        };
        auto ldB = [&](uint32_t s0, int ks){
            #pragma unroll
            for (int p = 0; p < 4; p++){
                const uint32_t ro = (uint32_t)(b_row + p*16)*ROWB + b_colb + ks*32;
                uint32_t r0,r1,r2,r3;
                ldm4(r0,r1,r2,r3, s0 + P_B + ro);
                bf[p*2][0]=r0; bf[p*2][1]=r1; bf[p*2+1][0]=r2; bf[p*2+1][1]=r3;
            }
        };
        auto mmaAll = [&](){
            #pragma unroll
            for (int t = 0; t < 2; t++){
                const uint32_t (*fa)[4] = (t == 1) ? al : ah;
                #pragma unroll
                for (int i = 0; i < 2; i++)
                    #pragma unroll
                    for (int j = 0; j < 8; j++)
                        mma16816h(acc[i][j], fa[i], bf[j]);
            }
        };

        load(0, 0);
        load(1, 1);
        for (int kt = 0; kt < KT; kt++){
            if (kt < KT-1) asm volatile("cp.async.wait_group 1;\n" ::: "memory");
            else           asm volatile("cp.async.wait_group 0;\n" ::: "memory");
            __syncthreads();
            if (kt + 2 < KT) load(kt + 2, (kt + 2) % NSTAGE);
            const uint32_t s0 = sb + (uint32_t)((kt % NSTAGE)*STAGEB);
            ldA(s0, 0); ldB(s0, 0);
            mmaAll();
            ldA(s0, 1); ldB(s0, 1);
            mmaAll();
        }
    } else {
        // ---- 1-term path: register fragment double-buffering ----
        Frag1 F0, F1;
        auto ldfrags = [&](uint32_t s0, int ks, Frag1& f){
            #pragma unroll
            for (int i = 0; i < 2; i++){
                const uint32_t ro = (uint32_t)(a_row + i*16)*ROWB + a_colb + ks*32;
                ldm4(f.a[i][0],f.a[i][1],f.a[i][2],f.a[i][3], s0 + ro);
            }
            #pragma unroll
            for (int p = 0; p < 4; p++){
                const uint32_t ro = (uint32_t)(b_row + p*16)*ROWB + b_colb + ks*32;
                uint32_t r0,r1,r2,r3;
                ldm4(r0,r1,r2,r3, s0 + P_B + ro);
                f.b[p*2][0]=r0; f.b[p*2][1]=r1; f.b[p*2+1][0]=r2; f.b[p*2+1][1]=r3;
            }
        };
        auto mmaAll = [&](const Frag1& f){
            #pragma unroll
            for (int i = 0; i < 2; i++)
                #pragma unroll
                for (int j = 0; j < 8; j++)
                    mma16816h(acc[i][j], f.a[i], f.b[j]);
        };

        load(0, 0);
        load(1, 1);
        asm volatile("cp.async.wait_group 1;\n" ::: "memory");
        __syncthreads();
        ldfrags(sb, 0, F0);

        for (int kt = 0; kt < KT; kt++){
            const uint32_t s0 = sb + (uint32_t)((kt % NSTAGE)*STAGEB);
            ldfrags(s0, 1, F1);      // LDSM for ks=1 in flight during...
            mmaAll(F0);              // ...this mma burst
            if (kt + 2 < KT) load(kt + 2, (kt + 2) % NSTAGE);
            if (kt + 1 < KT){
                if (kt + 2 < KT) asm volatile("cp.async.wait_group 1;\n" ::: "memory");
                else             asm volatile("cp.async.wait_group 0;\n" ::: "memory");
                __syncthreads();
                ldfrags(sb + (uint32_t)(((kt+1) % NSTAGE)*STAGEB), 0, F0);
            }
            mmaAll(F1);
        }
    }

    // epilogue: bias + elu -> fp16 (hi only, or hi/lo)
    const int gid = lane >> 2, tig = lane & 3;
    #pragma unroll
    for (int i = 0; i < 2; i++){
        const int mrow = m0 + wr*32 + i*16 + gid;
        #pragma unroll
        for (int j = 0; j < 8; j++){
            const int n = n0 + wc*64 + j*8 + tig*2;
            const float2 bv = *(const float2*)&bias[n];
            float v[4] = {acc[i][j][0] + bv.x, acc[i][j][1] + bv.y,
                          acc[i][j][2] + bv.x, acc[i][j][3] + bv.y};
            v[0]=eluf(v[0]); v[1]=eluf(v[1]); v[2]=eluf(v[2]); v[3]=eluf(v[3]);
            __half h[4], l[4];
            #pragma unroll
            for (int q = 0; q < 4; q++) split_f16(v[q], h[q], l[q]);
            const size_t o0 = (size_t)mrow*N + n, o1 = (size_t)(mrow+8)*N + n;
            *(__half2*)&Ch[o0] = *(__half2*)&h[0];
            *(__half2*)&Ch[o1] = *(__half2*)&h[2];
            if (STORELO){
                *(__half2*)&Cl[o0] = *(__half2*)&l[0];
                *(__half2*)&Cl[o1] = *(__half2*)&l[2];
            }
        }
    }
}

// fp32 x -> hi/lo fp16 planes
__global__ void cvt_x_k(const float* __restrict__ x,
                        __half* __restrict__ xh, __half* __restrict__ xl){
    size_t i = (size_t)blockIdx.x * blockDim.x + threadIdx.x;
    float4 v = ((const float4*)x)[i];
    __half h[4], l[4];
    split_f16(v.x, h[0], l[0]); split_f16(v.y, h[1], l[1]);
    split_f16(v.z, h[2], l[2]); split_f16(v.w, h[3], l[3]);
    ((uint2*)xh)[i] = *(uint2*)h;
    ((uint2*)xl)[i] = *(uint2*)l;
}

// w[k][n] fp32 -> wt [n][k] single fp16
__global__ void tr_cvt_k(const float* __restrict__ w,
                         __half* __restrict__ wt, int K, int N){
    __shared__ float t[32][33];
    const int n0 = blockIdx.x*32, k0 = blockIdx.y*32;
    #pragma unroll
    for (int r = threadIdx.y; r < 32; r += 8)
        t[r][threadIdx.x] = w[(size_t)(k0+r)*N + n0 + threadIdx.x];
    __syncthreads();
    #pragma unroll
    for (int r = threadIdx.y; r < 32; r += 8)
        wt[(size_t)(n0+r)*K + k0 + threadIdx.x] = __float2half(t[threadIdx.x][r]);
}

// layer 3: warp-per-row matvec (hi+lo reconstruct) + sigmoid + alpha
__global__ void final_k(const __half* __restrict__ hh, const __half* __restrict__ hl,
                        const float* __restrict__ w2, const float* __restrict__ b2,
                        float* __restrict__ out){
    const int gw   = (blockIdx.x*blockDim.x + threadIdx.x) >> 5;
    const int lane = threadIdx.x & 31;
    const __half* rh = hh + (size_t)gw * NHID;
    const __half* rl = hl + (size_t)gw * NHID;
    float s = 0.f;
    #pragma unroll
    for (int it = 0; it < NHID/256; it++){
        const int k = it*256 + lane*8;
        uint4 hv = *(const uint4*)(rh + k);
        uint4 lv = *(const uint4*)(rl + k);
        const __half2* hp = (const __half2*)&hv;
        const __half2* lp = (const __half2*)&lv;
        float4 wa = *(const float4*)(w2 + k);
        float4 wb = *(const float4*)(w2 + k + 4);
        float2 f0 = __half22float2(hp[0]), g0 = __half22float2(lp[0]);
        float2 f1 = __half22float2(hp[1]), g1 = __half22float2(lp[1]);
        float2 f2 = __half22float2(hp[2]), g2 = __half22float2(lp[2]);
        float2 f3 = __half22float2(hp[3]), g3 = __half22float2(lp[3]);
        s += (f0.x+g0.x)*wa.x + (f0.y+g0.y)*wa.y + (f1.x+g1.x)*wa.z + (f1.y+g1.y)*wa.w
           + (f2.x+g2.x)*wb.x + (f2.y+g2.y)*wb.y + (f3.x+g3.x)*wb.z + (f3.y+g3.y)*wb.w;
    }
    #pragma unroll
    for (int o = 16; o; o >>= 1) s += __shfl_xor_sync(0xffffffffu, s, o);
    if (lane == 0){
        const float z = s + b2[0];
        const float o = 1.f / (1.f + __expf(-z));
        out[gw] = o;
        float alpha;
        if      (o <= 0.2f) alpha = 0.1f - 0.5f*o;
        else if (o >= 0.8f) alpha = 0.5f*o - 0.4f;
        else                alpha = 0.f;
        out[BATCH + gw] = alpha;
    }
}

extern "C" void kernel_launch(void* const* d_in, const int* in_sizes, int n_in,
                              void* d_out, int out_size)
{
    const float* x  = (const float*)d_in[0];
    const float* W0 = (const float*)d_in[1];
    const float* b0 = (const float*)d_in[2];
    const float* W1 = (const float*)d_in[3];
    const float* b1 = (const float*)d_in[4];
    const float* W2 = (const float*)d_in[5];
    const float* b2 = (const float*)d_in[6];
    float* out = (float*)d_out;

    __half *xh,*xl,*w0,*w1,*h0,*h1h,*h1l;
    cudaGetSymbolAddress((void**)&xh,  g_xh);  cudaGetSymbolAddress((void**)&xl,  g_xl);
    cudaGetSymbolAddress((void**)&w0,  g_w0);  cudaGetSymbolAddress((void**)&w1,  g_w1);
    cudaGetSymbolAddress((void**)&h0,  g_h0);
    cudaGetSymbolAddress((void**)&h1h, g_h1h); cudaGetSymbolAddress((void**)&h1l, g_h1l);

    const int SMEM_L0 = NSTAGE * 3 * PLANE;   // 92160 (2-plane A + B)
    const int SMEM_L1 = NSTAGE * 2 * PLANE;   // 61440 (1-plane A + B)
    cudaFuncSetAttribute(gemm_split<1,0>, cudaFuncAttributeMaxDynamicSharedMemorySize, SMEM_L0);
    cudaFuncSetAttribute(gemm_split<0,1>, cudaFuncAttributeMaxDynamicSharedMemorySize, SMEM_L1);

    cvt_x_k<<<(BATCH*NIN/4)/256, 256>>>(x, xh, xl);
    tr_cvt_k<<<dim3(NHID/32, NIN/32),  dim3(32,8)>>>(W0, w0, NIN,  NHID);
    tr_cvt_k<<<dim3(NHID/32, NHID/32), dim3(32,8)>>>(W1, w1, NHID, NHID);

    // L0: 2-term (xh+xl)@W0 -> h0 single fp16 plane
    gemm_split<1,0><<<dim3(NHID/BN, BATCH/BM), 256, SMEM_L0>>>(
        xh, xl, w0, b0, h0, nullptr, BATCH, NHID, NIN);
    // L1: 1-term h0@W1 -> h1 hi/lo (frag double-buffered)
    gemm_split<0,1><<<dim3(NHID/BN, BATCH/BM), 256, SMEM_L1>>>(
        h0, nullptr, w1, b1, h1h, h1l, BATCH, NHID, NHID);

    final_k<<<BATCH/8, 256>>>(h1h, h1l, W2, b2, out);
}